// round 1
// baseline (speedup 1.0000x reference)
#include <cuda_runtime.h>
#include <math.h>

#define BB     2
#define NN     1024
#define DIMC   512
#define NHEADS 8
#define DHH    64
#define INNERC 512
#define FFC    2048
#define NDEPTH 2
#define MM     (BB*NN)
#define EPSF   1e-6f
#define ATT_SCALE 0.125f

// ---------------- scratch (device globals; no runtime allocation) ----------------
__device__ float2 g_x [MM*DIMC];      // residual stream
__device__ float2 g_hn[MM*DIMC];      // rmsnorm output
__device__ float2 g_q [MM*INNERC];    // Q (roped)
__device__ float2 g_kv[MM*2*INNERC];  // K (roped) | V
__device__ float2 g_o [MM*INNERC];    // attention output
__device__ float2 g_ff[MM*FFC];       // FF intermediate
__device__ float2 g_rope[NN*DHH];     // rope phase table

__device__ __forceinline__ float2 cmulf(float2 a, float2 b) {
    return make_float2(a.x*b.x - a.y*b.y, a.x*b.y + a.y*b.x);
}

// ---------------- rope table ----------------
__global__ void ct_rope_init() {
    int i = blockIdx.x*blockDim.x + threadIdx.x;
    if (i >= NN*DHH) return;
    int n = i / DHH, d = i % DHH;
    double inv = exp(-((double)d / (double)DHH) * log(10000.0));
    double fr  = (double)n * inv;
    g_rope[i] = make_float2((float)cos(fr), (float)sin(fr));
}

// ---------------- complex rmsnorm ----------------
__global__ __launch_bounds__(128) void ct_rmsnorm(const float2* __restrict__ in,
                                                  const float2* __restrict__ gamma,
                                                  float2* __restrict__ out) {
    int row = blockIdx.x;
    const float2* xr = in + row*DIMC;
    float ss = 0.f;
    for (int d = threadIdx.x; d < DIMC; d += 128) {
        float2 v = xr[d];
        ss = fmaf(v.x, v.x, ss);
        ss = fmaf(v.y, v.y, ss);
    }
#pragma unroll
    for (int off = 16; off; off >>= 1) ss += __shfl_xor_sync(0xffffffffu, ss, off);
    __shared__ float sred[4];
    if ((threadIdx.x & 31) == 0) sred[threadIdx.x >> 5] = ss;
    __syncthreads();
    ss = sred[0] + sred[1] + sred[2] + sred[3];
    float sc = rsqrtf(ss * (1.f/(float)DIMC) + EPSF);
    for (int d = threadIdx.x; d < DIMC; d += 128) {
        float2 v = xr[d];
        float2 g = gamma[d];
        out[row*DIMC + d] = make_float2(sc*(v.x*g.x - v.y*g.y),
                                        sc*(v.x*g.y + v.y*g.x));
    }
}

// ---------------- generic complex GEMM with fused epilogues ----------------
// C[m,n] = sum_k A[m,k] * W[k,n]   (complex), M fixed = MM
// epi: 0=Q rope   1=KV (rope cols<INNER)   2=residual add (C += r)
//      3=FF1: r+=bias; mag nonlinearity    4=FF2: C += r + bias
#define GBM 64
#define GBN 64
#define GBK 16

__global__ __launch_bounds__(256) void ct_cgemm(const float2* __restrict__ A,
                                                const float2* __restrict__ W,
                                                float2* __restrict__ C,
                                                int K, int NC, int epi,
                                                const float2* __restrict__ bias,
                                                const float* __restrict__ modb) {
    __shared__ float2 As[GBK][GBM + 1];
    __shared__ float2 Bs[GBK][GBN];
    int tid = threadIdx.x;
    int m0 = blockIdx.y * GBM;
    int n0 = blockIdx.x * GBN;
    int tx = tid & 15, ty = tid >> 4;

    float accx[4][4] = {}, accy[4][4] = {};

    for (int k0 = 0; k0 < K; k0 += GBK) {
#pragma unroll
        for (int i = 0; i < 4; i++) {           // A tile: 64x16
            int e = tid + i*256;
            int m = e >> 4, k = e & 15;
            As[k][m] = A[(m0 + m)*K + k0 + k];
        }
#pragma unroll
        for (int i = 0; i < 4; i++) {           // B tile: 16x64
            int e = tid + i*256;
            int k = e >> 6, n = e & 63;
            Bs[k][n] = W[(k0 + k)*NC + n0 + n];
        }
        __syncthreads();
#pragma unroll
        for (int kk = 0; kk < GBK; kk++) {
            float2 a[4], bb[4];
#pragma unroll
            for (int i = 0; i < 4; i++) a[i]  = As[kk][ty + 16*i];
#pragma unroll
            for (int j = 0; j < 4; j++) bb[j] = Bs[kk][tx + 16*j];
#pragma unroll
            for (int i = 0; i < 4; i++)
#pragma unroll
                for (int j = 0; j < 4; j++) {
                    accx[i][j] = fmaf(a[i].x,  bb[j].x, accx[i][j]);
                    accx[i][j] = fmaf(-a[i].y, bb[j].y, accx[i][j]);
                    accy[i][j] = fmaf(a[i].x,  bb[j].y, accy[i][j]);
                    accy[i][j] = fmaf(a[i].y,  bb[j].x, accy[i][j]);
                }
        }
        __syncthreads();
    }

#pragma unroll
    for (int i = 0; i < 4; i++) {
        int m = m0 + ty + 16*i;
#pragma unroll
        for (int j = 0; j < 4; j++) {
            int n = n0 + tx + 16*j;
            float2 r = make_float2(accx[i][j], accy[i][j]);
            int idx = m*NC + n;
            if (epi == 0) {
                float2 ph = g_rope[(m & (NN-1))*DHH + (n & (DHH-1))];
                C[idx] = cmulf(r, ph);
            } else if (epi == 1) {
                if (n < INNERC) {
                    float2 ph = g_rope[(m & (NN-1))*DHH + (n & (DHH-1))];
                    r = cmulf(r, ph);
                }
                C[idx] = r;
            } else if (epi == 2) {
                float2 c = C[idx];
                C[idx] = make_float2(c.x + r.x, c.y + r.y);
            } else if (epi == 3) {
                float2 bv = bias[n];
                r.x += bv.x; r.y += bv.y;
                float mag = sqrtf(r.x*r.x + r.y*r.y);
                float t = fmaxf(mag + *modb, 0.f);
                float cl = t*t;
                if (mag > 0.f) {
                    float s = cl / mag;
                    r.x *= s; r.y *= s;
                } else {
                    r.x = cl; r.y = 0.f;
                }
                C[idx] = r;
            } else { // epi == 4
                float2 bv = bias[n];
                float2 c = C[idx];
                C[idx] = make_float2(c.x + r.x + bv.x, c.y + r.y + bv.y);
            }
        }
    }
}

// ---------------- fused complex attention (4 real attentions, online softmax) ----
// grid: (B*H, N/AQT), block 256 (8 warps).
// warp -> (variant = warp&3, qgroup = warp>>2), each warp owns 4 query rows.
// variant v: q-comp = (v<2) ? re : im ; k-comp = (v&1) ? -im : re ; v-comp = (v<2) ? re : im
// out.re = o0 - o3 ; out.im = o1 + o2
#define AQT 8
#define ABC 32
#define RPW 4   // rows per warp

__global__ __launch_bounds__(256) void ct_attention() {
    __shared__ float2 shK[ABC][DHH];
    __shared__ float2 shV[ABC][DHH];
    __shared__ float2 shQ[AQT][DHH];
    __shared__ float  shO[AQT][4][DHH];

    int bh = blockIdx.x;
    int b  = bh / NHEADS;
    int hh = bh % NHEADS;
    int qbase_glob = blockIdx.y * AQT;
    int tid  = threadIdx.x;
    int warp = tid >> 5;
    int lane = tid & 31;
    int variant = warp & 3;
    int qg = warp >> 2;          // 0..1
    int qbase = qg * RPW;        // local q row base for this warp

    // load Q rows for this block
    for (int e = tid; e < AQT*DHH; e += 256) {
        int qi = e >> 6, d = e & 63;
        shQ[qi][d] = g_q[(b*NN + qbase_glob + qi)*INNERC + hh*DHH + d];
    }
    __syncthreads();

    // per-lane q components for 4 rows (dims 2*lane, 2*lane+1)
    float q0[RPW], q1[RPW];
#pragma unroll
    for (int r = 0; r < RPW; r++) {
        float2 c0 = shQ[qbase + r][2*lane];
        float2 c1 = shQ[qbase + r][2*lane + 1];
        if (variant < 2) { q0[r] = c0.x; q1[r] = c1.x; }
        else             { q0[r] = c0.y; q1[r] = c1.y; }
    }

    float mrow[RPW], lrow[RPW], a0[RPW], a1[RPW];
#pragma unroll
    for (int r = 0; r < RPW; r++) { mrow[r] = -1e30f; lrow[r] = 0.f; a0[r] = 0.f; a1[r] = 0.f; }

    for (int kt = 0; kt < NN; kt += ABC) {
        __syncthreads();
        for (int e = tid; e < ABC*DHH; e += 256) {
            int j = e >> 6, d = e & 63;
            int base = (b*NN + kt + j)*2*INNERC + hh*DHH + d;
            shK[j][d] = g_kv[base];
            shV[j][d] = g_kv[base + INNERC];
        }
        __syncthreads();

        for (int j = 0; j < ABC; j++) {
            float4 k4 = *reinterpret_cast<const float4*>(&shK[j][2*lane]);
            float kk0 = (variant & 1) ? -k4.y : k4.x;
            float kk1 = (variant & 1) ? -k4.w : k4.z;
            float4 v4 = *reinterpret_cast<const float4*>(&shV[j][2*lane]);
            float vv0 = (variant < 2) ? v4.x : v4.y;
            float vv1 = (variant < 2) ? v4.z : v4.w;

            float s[RPW];
#pragma unroll
            for (int r = 0; r < RPW; r++) s[r] = fmaf(q0[r], kk0, q1[r]*kk1);
#pragma unroll
            for (int off = 16; off; off >>= 1)
#pragma unroll
                for (int r = 0; r < RPW; r++)
                    s[r] += __shfl_xor_sync(0xffffffffu, s[r], off);
#pragma unroll
            for (int r = 0; r < RPW; r++) {
                float sv = s[r] * ATT_SCALE;
                float nm = fmaxf(mrow[r], sv);
                float corr = __expf(mrow[r] - nm);
                float p    = __expf(sv - nm);
                lrow[r] = lrow[r]*corr + p;
                a0[r]   = a0[r]*corr + p*vv0;
                a1[r]   = a1[r]*corr + p*vv1;
                mrow[r] = nm;
            }
        }
    }

#pragma unroll
    for (int r = 0; r < RPW; r++) {
        float inv = 1.f / lrow[r];
        shO[qbase + r][variant][2*lane]     = a0[r]*inv;
        shO[qbase + r][variant][2*lane + 1] = a1[r]*inv;
    }
    __syncthreads();

    for (int e = tid; e < AQT*DHH; e += 256) {
        int qi = e >> 6, d = e & 63;
        float re = shO[qi][0][d] - shO[qi][3][d];
        float im = shO[qi][1][d] + shO[qi][2][d];
        g_o[(b*NN + qbase_glob + qi)*INNERC + hh*DHH + d] = make_float2(re, im);
    }
}

// ---------------- launcher ----------------
extern "C" void kernel_launch(void* const* d_in, const int* in_sizes, int n_in,
                              void* d_out, int out_size) {
    (void)in_sizes; (void)n_in; (void)out_size;
    const float2* x          = (const float2*)d_in[0];
    const float2* gamma_attn = (const float2*)d_in[1];
    const float2* Wq         = (const float2*)d_in[2];
    const float2* Wkv        = (const float2*)d_in[3];
    const float2* Wo         = (const float2*)d_in[4];
    const float2* gamma_ff   = (const float2*)d_in[5];
    const float2* W1         = (const float2*)d_in[6];
    const float2* b1         = (const float2*)d_in[7];
    const float*  modb       = (const float*)d_in[8];
    const float2* W2         = (const float2*)d_in[9];
    const float2* b2         = (const float2*)d_in[10];
    const float2* gfin       = (const float2*)d_in[11];

    float2 *px, *phn, *pq, *pkv, *po, *pff;
    cudaGetSymbolAddress((void**)&px,  g_x);
    cudaGetSymbolAddress((void**)&phn, g_hn);
    cudaGetSymbolAddress((void**)&pq,  g_q);
    cudaGetSymbolAddress((void**)&pkv, g_kv);
    cudaGetSymbolAddress((void**)&po,  g_o);
    cudaGetSymbolAddress((void**)&pff, g_ff);

    cudaMemcpyAsync(px, x, sizeof(float2)*MM*DIMC, cudaMemcpyDeviceToDevice);
    ct_rope_init<<<(NN*DHH + 255)/256, 256>>>();

    for (int l = 0; l < NDEPTH; l++) {
        ct_rmsnorm<<<MM, 128>>>(px, gamma_attn + l*DIMC, phn);
        ct_cgemm<<<dim3(INNERC/GBN,   MM/GBM), 256>>>(phn, Wq  + (size_t)l*DIMC*INNERC,   pq,  DIMC, INNERC,   0, nullptr, nullptr);
        ct_cgemm<<<dim3(2*INNERC/GBN, MM/GBM), 256>>>(phn, Wkv + (size_t)l*DIMC*2*INNERC, pkv, DIMC, 2*INNERC, 1, nullptr, nullptr);
        ct_attention<<<dim3(BB*NHEADS, NN/AQT), 256>>>();
        ct_cgemm<<<dim3(DIMC/GBN, MM/GBM), 256>>>(po, Wo + (size_t)l*INNERC*DIMC, px, INNERC, DIMC, 2, nullptr, nullptr);
        ct_rmsnorm<<<MM, 128>>>(px, gamma_ff + l*DIMC, phn);
        ct_cgemm<<<dim3(FFC/GBN,  MM/GBM), 256>>>(phn, W1 + (size_t)l*DIMC*FFC, pff, DIMC, FFC, 3, b1 + l*FFC,  modb + l);
        ct_cgemm<<<dim3(DIMC/GBN, MM/GBM), 256>>>(pff, W2 + (size_t)l*FFC*DIMC, px,  FFC,  DIMC, 4, b2 + l*DIMC, nullptr);
    }
    ct_rmsnorm<<<MM, 128>>>(px, gfin, (float2*)d_out);
}

// round 2
// speedup vs baseline: 2.8487x; 2.8487x over previous
#include <cuda_runtime.h>
#include <math.h>
#include <stdint.h>

#define BB     2
#define NN     1024
#define DIMC   512
#define NHEADS 8
#define DHH    64
#define INNERC 512
#define FFC    2048
#define NDEPTH 2
#define MM     (BB*NN)
#define EPSF   1e-6f
#define ATT_SCALE 0.125f

// ---------------- scratch (device globals; no runtime allocation) ----------------
__device__ float2 g_x [MM*DIMC];      // residual stream
__device__ float2 g_hn[MM*DIMC];      // rmsnorm output
__device__ float2 g_q [MM*INNERC];    // Q (roped)
__device__ float2 g_kv[MM*2*INNERC];  // K (roped) | V
__device__ float2 g_o [MM*INNERC];    // attention output (combined)
__device__ float2 g_ff[MM*FFC];       // FF intermediate / attention variant planes
__device__ float2 g_rope[NN*DHH];     // rope phase table

__device__ __forceinline__ float2 cmulf(float2 a, float2 b) {
    return make_float2(a.x*b.x - a.y*b.y, a.x*b.y + a.y*b.x);
}

__device__ __forceinline__ uint32_t f2tf32(float x) {
    uint32_t u;
    asm("cvt.rna.tf32.f32 %0, %1;" : "=r"(u) : "f"(x));
    return u;
}

// ---------------- rope table ----------------
__global__ void ct_rope_init() {
    int i = blockIdx.x*blockDim.x + threadIdx.x;
    if (i >= NN*DHH) return;
    int n = i / DHH, d = i % DHH;
    double inv = exp(-((double)d / (double)DHH) * log(10000.0));
    double fr  = (double)n * inv;
    g_rope[i] = make_float2((float)cos(fr), (float)sin(fr));
}

// ---------------- complex rmsnorm ----------------
__global__ __launch_bounds__(128) void ct_rmsnorm(const float2* __restrict__ in,
                                                  const float2* __restrict__ gamma,
                                                  float2* __restrict__ out) {
    int row = blockIdx.x;
    const float2* xr = in + row*DIMC;
    float ss = 0.f;
    for (int d = threadIdx.x; d < DIMC; d += 128) {
        float2 v = xr[d];
        ss = fmaf(v.x, v.x, ss);
        ss = fmaf(v.y, v.y, ss);
    }
#pragma unroll
    for (int off = 16; off; off >>= 1) ss += __shfl_xor_sync(0xffffffffu, ss, off);
    __shared__ float sred[4];
    if ((threadIdx.x & 31) == 0) sred[threadIdx.x >> 5] = ss;
    __syncthreads();
    ss = sred[0] + sred[1] + sred[2] + sred[3];
    float sc = rsqrtf(ss * (1.f/(float)DIMC) + EPSF);
    for (int d = threadIdx.x; d < DIMC; d += 128) {
        float2 v = xr[d];
        float2 g = gamma[d];
        out[row*DIMC + d] = make_float2(sc*(v.x*g.x - v.y*g.y),
                                        sc*(v.x*g.y + v.y*g.x));
    }
}

// ---------------- tf32 tensor-core complex GEMM with fused epilogues ----------
// C[m,n] = sum_k A[m,k]*W[k,n] (complex). BM=128, BN=64, BK=16. 256 thr (8 warps).
// warp tile 32x32: 2 m16 tiles x 4 n8 tiles, mma.m16n8k8.tf32.
// epi: 0=Q rope  1=KV (rope cols<INNER)  2=residual add  3=FF1 bias+mag nonlin  4=FF2 +bias+res
#define TBM 128
#define TBN 64
#define TBK 16
#define APAD 136   // TBM + 8  (fragment stride ≡ 8 mod 32 → conflict-free)
#define BPAD 72    // TBN + 8

__device__ __forceinline__ void mma_tf32(float* d, const uint32_t* a, const uint32_t* b) {
    asm volatile(
        "mma.sync.aligned.m16n8k8.row.col.f32.tf32.tf32.f32 "
        "{%0,%1,%2,%3},{%4,%5,%6,%7},{%8,%9},{%0,%1,%2,%3};"
        : "+f"(d[0]), "+f"(d[1]), "+f"(d[2]), "+f"(d[3])
        : "r"(a[0]), "r"(a[1]), "r"(a[2]), "r"(a[3]), "r"(b[0]), "r"(b[1]));
}

__device__ __forceinline__ void epilog(float2* __restrict__ C, int NC, int m, int n,
                                       float re, float im, int epi,
                                       const float2* __restrict__ bias,
                                       const float* __restrict__ modb) {
    int idx = m*NC + n;
    float2 r = make_float2(re, im);
    if (epi == 0) {
        float2 ph = g_rope[(m & (NN-1))*DHH + (n & (DHH-1))];
        C[idx] = cmulf(r, ph);
    } else if (epi == 1) {
        if (n < INNERC) {
            float2 ph = g_rope[(m & (NN-1))*DHH + (n & (DHH-1))];
            r = cmulf(r, ph);
        }
        C[idx] = r;
    } else if (epi == 2) {
        float2 c = C[idx];
        C[idx] = make_float2(c.x + r.x, c.y + r.y);
    } else if (epi == 3) {
        float2 bv = bias[n];
        r.x += bv.x; r.y += bv.y;
        float mag = sqrtf(r.x*r.x + r.y*r.y);
        float t = fmaxf(mag + *modb, 0.f);
        float cl = t*t;
        if (mag > 0.f) {
            float s = cl / mag;
            r.x *= s; r.y *= s;
        } else {
            r.x = cl; r.y = 0.f;
        }
        C[idx] = r;
    } else { // 4
        float2 bv = bias[n];
        float2 c = C[idx];
        C[idx] = make_float2(c.x + r.x + bv.x, c.y + r.y + bv.y);
    }
}

__global__ __launch_bounds__(256) void ct_cgemm_tc(const float2* __restrict__ A,
                                                   const float2* __restrict__ W,
                                                   float2* __restrict__ C,
                                                   int K, int NC, int epi,
                                                   const float2* __restrict__ bias,
                                                   const float* __restrict__ modb) {
    __shared__ float Asr[TBK][APAD];
    __shared__ float Asi[TBK][APAD];
    __shared__ float Bsr[TBK][BPAD];
    __shared__ float Bsi[TBK][BPAD];

    int tid  = threadIdx.x;
    int warp = tid >> 5;
    int lane = tid & 31;
    int g    = lane >> 2;    // groupID 0..7
    int tg   = lane & 3;     // threadInGroup 0..3
    int warp_m = warp & 3;   // 4 warps over M
    int warp_n = warp >> 2;  // 2 warps over N
    int m0 = blockIdx.y * TBM;
    int n0 = blockIdx.x * TBN;

    float cr[2][4][4] = {};
    float ci[2][4][4] = {};

    for (int k0 = 0; k0 < K; k0 += TBK) {
        // stage A tile (128x16 complex): 1024 float4 = 4 per thread
#pragma unroll
        for (int i = 0; i < 4; i++) {
            int idx = tid*4 + i;
            int r = idx >> 3;          // row 0..127
            int c4 = idx & 7;          // float4 index (2 complex)
            float4 f = *reinterpret_cast<const float4*>(&A[(size_t)(m0 + r)*K + k0 + c4*2]);
            int k = c4*2;
            Asr[k][r]   = __uint_as_float(f2tf32(f.x));
            Asi[k][r]   = __uint_as_float(f2tf32(f.y));
            Asr[k+1][r] = __uint_as_float(f2tf32(f.z));
            Asi[k+1][r] = __uint_as_float(f2tf32(f.w));
        }
        // stage B tile (16x64 complex): 512 float4 = 2 per thread
#pragma unroll
        for (int i = 0; i < 2; i++) {
            int idx = tid + i*256;
            int r = idx >> 5;          // k row 0..15
            int c4 = idx & 31;
            float4 f = *reinterpret_cast<const float4*>(&W[(size_t)(k0 + r)*NC + n0 + c4*2]);
            int n = c4*2;
            Bsr[r][n]   = __uint_as_float(f2tf32(f.x));
            Bsi[r][n]   = __uint_as_float(f2tf32(f.y));
            Bsr[r][n+1] = __uint_as_float(f2tf32(f.z));
            Bsi[r][n+1] = __uint_as_float(f2tf32(f.w));
        }
        __syncthreads();

#pragma unroll
        for (int ks = 0; ks < TBK; ks += 8) {
            uint32_t ar[2][4], ai[2][4], nai[2][4];
            uint32_t br[4][2], bi[4][2];
#pragma unroll
            for (int mt = 0; mt < 2; mt++) {
                int mb = warp_m*32 + mt*16;
                ar[mt][0] = __float_as_uint(Asr[ks+tg  ][mb + g    ]);
                ar[mt][1] = __float_as_uint(Asr[ks+tg  ][mb + g + 8]);
                ar[mt][2] = __float_as_uint(Asr[ks+tg+4][mb + g    ]);
                ar[mt][3] = __float_as_uint(Asr[ks+tg+4][mb + g + 8]);
                ai[mt][0] = __float_as_uint(Asi[ks+tg  ][mb + g    ]);
                ai[mt][1] = __float_as_uint(Asi[ks+tg  ][mb + g + 8]);
                ai[mt][2] = __float_as_uint(Asi[ks+tg+4][mb + g    ]);
                ai[mt][3] = __float_as_uint(Asi[ks+tg+4][mb + g + 8]);
#pragma unroll
                for (int t = 0; t < 4; t++) nai[mt][t] = ai[mt][t] ^ 0x80000000u;
            }
#pragma unroll
            for (int nt = 0; nt < 4; nt++) {
                int nb = warp_n*32 + nt*8;
                br[nt][0] = __float_as_uint(Bsr[ks+tg  ][nb + g]);
                br[nt][1] = __float_as_uint(Bsr[ks+tg+4][nb + g]);
                bi[nt][0] = __float_as_uint(Bsi[ks+tg  ][nb + g]);
                bi[nt][1] = __float_as_uint(Bsi[ks+tg+4][nb + g]);
            }
#pragma unroll
            for (int mt = 0; mt < 2; mt++)
#pragma unroll
                for (int nt = 0; nt < 4; nt++) {
                    mma_tf32(cr[mt][nt], ar[mt],  br[nt]);
                    mma_tf32(cr[mt][nt], nai[mt], bi[nt]);
                    mma_tf32(ci[mt][nt], ar[mt],  bi[nt]);
                    mma_tf32(ci[mt][nt], ai[mt],  br[nt]);
                }
        }
        __syncthreads();
    }

    // epilogue
#pragma unroll
    for (int mt = 0; mt < 2; mt++)
#pragma unroll
        for (int nt = 0; nt < 4; nt++)
#pragma unroll
            for (int c = 0; c < 4; c++) {
                int row = m0 + warp_m*32 + mt*16 + g + ((c >= 2) ? 8 : 0);
                int col = n0 + warp_n*32 + nt*8 + 2*tg + (c & 1);
                epilog(C, NC, row, col, cr[mt][nt][c], ci[mt][nt][c], epi, bias, modb);
            }
}

// ---------------- attention: GEMM-structured, per-variant, no online max ---------
// grid (bh=16, qt=16, variant=4), block 256 (16x16).
// Scores bounded (~|s|<5) so exp(s) directly; normalize by row sum at the end.
#define ATQ 64
#define ATK 32

__global__ __launch_bounds__(256) void ct_attention2(float* __restrict__ planes) {
    __shared__ float Qs[ATQ][DHH + 1];
    __shared__ float Ks[ATK][DHH + 2];   // reused as Ps after S is computed
    __shared__ float Vs[ATK][DHH + 2];
    __shared__ float red[ATQ][17];
    __shared__ float lsum[ATQ];

    int bh = blockIdx.x;
    int b  = bh >> 3;
    int h  = bh & 7;
    int q0 = blockIdx.y * ATQ;
    int v  = blockIdx.z;
    int tid = threadIdx.x;
    int tx = tid & 15, ty = tid >> 4;

    // load Q component
    for (int e = tid; e < ATQ*DHH; e += 256) {
        int i = e >> 6, d = e & 63;
        float2 c = g_q[(size_t)(b*NN + q0 + i)*INNERC + h*DHH + d];
        Qs[i][d] = (v < 2) ? c.x : c.y;
    }
    if (tid < ATQ) lsum[tid] = 0.f;

    float o[4][4] = {};
    __syncthreads();

    for (int kt = 0; kt < NN; kt += ATK) {
        // load K,V components for this tile
        for (int e = tid; e < ATK*DHH; e += 256) {
            int j = e >> 6, d = e & 63;
            const float2* base = &g_kv[(size_t)(b*NN + kt + j)*2*INNERC + h*DHH + d];
            float2 kc = base[0];
            float2 vc = base[INNERC];
            Ks[j][d] = (v & 1) ? -kc.y : kc.x;
            Vs[j][d] = (v < 2) ? vc.x : vc.y;
        }
        __syncthreads();

        // S = Q·K^T  (64q x 32k), thread tile 4x2
        float s[4][2] = {};
#pragma unroll 8
        for (int d = 0; d < DHH; d++) {
            float a[4], bb[2];
#pragma unroll
            for (int ii = 0; ii < 4; ii++) a[ii] = Qs[ty + 16*ii][d];
#pragma unroll
            for (int jj = 0; jj < 2; jj++) bb[jj] = Ks[tx + 16*jj][d];
#pragma unroll
            for (int ii = 0; ii < 4; ii++)
#pragma unroll
                for (int jj = 0; jj < 2; jj++)
                    s[ii][jj] = fmaf(a[ii], bb[jj], s[ii][jj]);
        }
        __syncthreads();   // done reading Ks; about to overwrite with P

        // P = exp(S*scale) into Ks; partial row sums
        float part[4];
#pragma unroll
        for (int ii = 0; ii < 4; ii++) {
            part[ii] = 0.f;
#pragma unroll
            for (int jj = 0; jj < 2; jj++) {
                float p = __expf(s[ii][jj] * ATT_SCALE);
                Ks[tx + 16*jj][ty + 16*ii] = p;   // store transposed: Ps[j][i] -> wait, see below
                part[ii] += p;
            }
        }
        // NOTE: we stored P transposed: Ks[j][i] = P[i][j]. PV reads P[i][j] = Ks[j][i].
#pragma unroll
        for (int ii = 0; ii < 4; ii++) red[ty + 16*ii][tx] = part[ii];
        __syncthreads();

        if (tid < ATQ) {
            float t = 0.f;
#pragma unroll
            for (int c = 0; c < 16; c++) t += red[tid][c];
            lsum[tid] += t;
        }

        // O += P·V : o[ii][jj] over (i = ty+16ii, d = tx+16jj)
#pragma unroll 4
        for (int j = 0; j < ATK; j++) {
            float a[4], bb[4];
#pragma unroll
            for (int ii = 0; ii < 4; ii++) a[ii] = Ks[j][ty + 16*ii];  // P[i][j]
#pragma unroll
            for (int jj = 0; jj < 4; jj++) bb[jj] = Vs[j][tx + 16*jj];
#pragma unroll
            for (int ii = 0; ii < 4; ii++)
#pragma unroll
                for (int jj = 0; jj < 4; jj++)
                    o[ii][jj] = fmaf(a[ii], bb[jj], o[ii][jj]);
        }
        __syncthreads();
    }

    // write normalized plane
    float* outp = planes + (size_t)v * MM * INNERC;
#pragma unroll
    for (int ii = 0; ii < 4; ii++) {
        int i = ty + 16*ii;
        float inv = 1.f / lsum[i];
#pragma unroll
        for (int jj = 0; jj < 4; jj++) {
            int d = tx + 16*jj;
            outp[(size_t)(b*NN + q0 + i)*INNERC + h*DHH + d] = o[ii][jj] * inv;
        }
    }
}

// combine 4 variant planes: re = o0 - o3, im = o1 + o2
__global__ __launch_bounds__(256) void ct_combine(const float* __restrict__ planes) {
    int idx = blockIdx.x*blockDim.x + threadIdx.x;
    if (idx >= MM*INNERC) return;
    const size_t P = (size_t)MM * INNERC;
    g_o[idx] = make_float2(planes[idx]       - planes[3*P + idx],
                           planes[P + idx]   + planes[2*P + idx]);
}

// ---------------- launcher ----------------
extern "C" void kernel_launch(void* const* d_in, const int* in_sizes, int n_in,
                              void* d_out, int out_size) {
    (void)in_sizes; (void)n_in; (void)out_size;
    const float2* x          = (const float2*)d_in[0];
    const float2* gamma_attn = (const float2*)d_in[1];
    const float2* Wq         = (const float2*)d_in[2];
    const float2* Wkv        = (const float2*)d_in[3];
    const float2* Wo         = (const float2*)d_in[4];
    const float2* gamma_ff   = (const float2*)d_in[5];
    const float2* W1         = (const float2*)d_in[6];
    const float2* b1         = (const float2*)d_in[7];
    const float*  modb       = (const float*)d_in[8];
    const float2* W2         = (const float2*)d_in[9];
    const float2* b2         = (const float2*)d_in[10];
    const float2* gfin       = (const float2*)d_in[11];

    float2 *px, *phn, *pq, *pkv, *po, *pff;
    cudaGetSymbolAddress((void**)&px,  g_x);
    cudaGetSymbolAddress((void**)&phn, g_hn);
    cudaGetSymbolAddress((void**)&pq,  g_q);
    cudaGetSymbolAddress((void**)&pkv, g_kv);
    cudaGetSymbolAddress((void**)&po,  g_o);
    cudaGetSymbolAddress((void**)&pff, g_ff);
    float* planes = (float*)pff;

    cudaMemcpyAsync(px, x, sizeof(float2)*MM*DIMC, cudaMemcpyDeviceToDevice);
    ct_rope_init<<<(NN*DHH + 255)/256, 256>>>();

    for (int l = 0; l < NDEPTH; l++) {
        ct_rmsnorm<<<MM, 128>>>(px, gamma_attn + l*DIMC, phn);
        ct_cgemm_tc<<<dim3(INNERC/TBN,   MM/TBM), 256>>>(phn, Wq  + (size_t)l*DIMC*INNERC,   pq,  DIMC, INNERC,   0, nullptr, nullptr);
        ct_cgemm_tc<<<dim3(2*INNERC/TBN, MM/TBM), 256>>>(phn, Wkv + (size_t)l*DIMC*2*INNERC, pkv, DIMC, 2*INNERC, 1, nullptr, nullptr);
        ct_attention2<<<dim3(BB*NHEADS, NN/ATQ, 4), 256>>>(planes);
        ct_combine<<<(MM*INNERC + 255)/256, 256>>>(planes);
        ct_cgemm_tc<<<dim3(DIMC/TBN, MM/TBM), 256>>>(po, Wo + (size_t)l*INNERC*DIMC, px, INNERC, DIMC, 2, nullptr, nullptr);
        ct_rmsnorm<<<MM, 128>>>(px, gamma_ff + l*DIMC, phn);
        ct_cgemm_tc<<<dim3(FFC/TBN,  MM/TBM), 256>>>(phn, W1 + (size_t)l*DIMC*FFC, pff, DIMC, FFC, 3, b1 + l*FFC,  modb + l);
        ct_cgemm_tc<<<dim3(DIMC/TBN, MM/TBM), 256>>>(pff, W2 + (size_t)l*FFC*DIMC, px,  FFC,  DIMC, 4, b2 + l*DIMC, nullptr);
    }
    ct_rmsnorm<<<MM, 128>>>(px, gfin, (float2*)d_out);
}

// round 4
// speedup vs baseline: 3.5621x; 1.2504x over previous
#include <cuda_runtime.h>
#include <math.h>
#include <stdint.h>

#define BB     2
#define NN     1024
#define DIMC   512
#define NHEADS 8
#define DHH    64
#define INNERC 512
#define FFC    2048
#define NDEPTH 2
#define MM     (BB*NN)
#define EPSF   1e-6f
#define ATT_SCALE 0.125f

// ---------------- scratch ----------------
__device__ float2 g_x [MM*DIMC];
__device__ float2 g_hn[MM*DIMC];
__device__ float2 g_q [MM*INNERC];
__device__ float2 g_kv[MM*2*INNERC];
__device__ float2 g_o [MM*INNERC];
__device__ float2 g_ff[MM*FFC];       // FF intermediate / attention variant planes
__device__ float2 g_rope[NN*DHH];

__device__ __forceinline__ float2 cmulf(float2 a, float2 b) {
    return make_float2(a.x*b.x - a.y*b.y, a.x*b.y + a.y*b.x);
}
__device__ __forceinline__ uint32_t f2tf32(float x) {
    uint32_t u;
    asm("cvt.rna.tf32.f32 %0, %1;" : "=r"(u) : "f"(x));
    return u;
}
__device__ __forceinline__ float tf32f(float x) {
    return __uint_as_float(f2tf32(x));
}
__device__ __forceinline__ void mma_tf32(float* d, const uint32_t* a, const uint32_t* b) {
    asm volatile(
        "mma.sync.aligned.m16n8k8.row.col.f32.tf32.tf32.f32 "
        "{%0,%1,%2,%3},{%4,%5,%6,%7},{%8,%9},{%0,%1,%2,%3};"
        : "+f"(d[0]), "+f"(d[1]), "+f"(d[2]), "+f"(d[3])
        : "r"(a[0]), "r"(a[1]), "r"(a[2]), "r"(a[3]), "r"(b[0]), "r"(b[1]));
}

// ---------------- rope table ----------------
__global__ void ct_rope_init() {
    int i = blockIdx.x*blockDim.x + threadIdx.x;
    if (i >= NN*DHH) return;
    int n = i / DHH, d = i % DHH;
    double inv = exp(-((double)d / (double)DHH) * log(10000.0));
    double fr  = (double)n * inv;
    g_rope[i] = make_float2((float)cos(fr), (float)sin(fr));
}

// ---------------- complex rmsnorm ----------------
__global__ __launch_bounds__(128) void ct_rmsnorm(const float2* __restrict__ in,
                                                  const float2* __restrict__ gamma,
                                                  float2* __restrict__ out) {
    int row = blockIdx.x;
    const float2* xr = in + row*DIMC;
    float ss = 0.f;
    for (int d = threadIdx.x; d < DIMC; d += 128) {
        float2 v = xr[d];
        ss = fmaf(v.x, v.x, ss);
        ss = fmaf(v.y, v.y, ss);
    }
#pragma unroll
    for (int off = 16; off; off >>= 1) ss += __shfl_xor_sync(0xffffffffu, ss, off);
    __shared__ float sred[4];
    if ((threadIdx.x & 31) == 0) sred[threadIdx.x >> 5] = ss;
    __syncthreads();
    ss = sred[0] + sred[1] + sred[2] + sred[3];
    float sc = rsqrtf(ss * (1.f/(float)DIMC) + EPSF);
    for (int d = threadIdx.x; d < DIMC; d += 128) {
        float2 v = xr[d];
        float2 g = gamma[d];
        out[row*DIMC + d] = make_float2(sc*(v.x*g.x - v.y*g.y),
                                        sc*(v.x*g.y + v.y*g.x));
    }
}

// ---------------- tf32 tensor-core complex GEMM (float2 smem planes) ---------
#define TBM 128
#define TBN 64
#define TBK 16
#define APAD2 132   // float2 stride; ≡4 mod 16 → conflict-free LDS.64 frag reads
#define BPAD2 68

__device__ __forceinline__ void epilog(float2* __restrict__ C, int NC, int m, int n,
                                       float re, float im, int epi,
                                       const float2* __restrict__ bias,
                                       const float* __restrict__ modb) {
    int idx = m*NC + n;
    float2 r = make_float2(re, im);
    if (epi == 0) {
        float2 ph = g_rope[(m & (NN-1))*DHH + (n & (DHH-1))];
        C[idx] = cmulf(r, ph);
    } else if (epi == 1) {
        if (n < INNERC) {
            float2 ph = g_rope[(m & (NN-1))*DHH + (n & (DHH-1))];
            r = cmulf(r, ph);
        }
        C[idx] = r;
    } else if (epi == 2) {
        float2 c = C[idx];
        C[idx] = make_float2(c.x + r.x, c.y + r.y);
    } else if (epi == 3) {
        float2 bv = bias[n];
        r.x += bv.x; r.y += bv.y;
        float mag = sqrtf(r.x*r.x + r.y*r.y);
        float t = fmaxf(mag + *modb, 0.f);
        float cl = t*t;
        if (mag > 0.f) {
            float s = cl / mag;
            r.x *= s; r.y *= s;
        } else {
            r.x = cl; r.y = 0.f;
        }
        C[idx] = r;
    } else {
        float2 bv = bias[n];
        float2 c = C[idx];
        C[idx] = make_float2(c.x + r.x + bv.x, c.y + r.y + bv.y);
    }
}

__global__ __launch_bounds__(256) void ct_cgemm_tc(const float2* __restrict__ A,
                                                   const float2* __restrict__ W,
                                                   float2* __restrict__ C,
                                                   int K, int NC, int epi,
                                                   const float2* __restrict__ bias,
                                                   const float* __restrict__ modb) {
    __shared__ float2 As[TBK][APAD2];   // (re,im) interleaved, [k][m]
    __shared__ float2 Bs[TBK][BPAD2];   // [k][n]

    int tid  = threadIdx.x;
    int warp = tid >> 5;
    int lane = tid & 31;
    int g    = lane >> 2;
    int tg   = lane & 3;
    int warp_m = warp & 3;
    int warp_n = warp >> 2;
    int m0 = blockIdx.y * TBM;
    int n0 = blockIdx.x * TBN;

    float cr[2][4][4] = {};
    float ci[2][4][4] = {};

    for (int k0 = 0; k0 < K; k0 += TBK) {
#pragma unroll
        for (int i = 0; i < 4; i++) {           // A tile 128x16 complex
            int idx = tid*4 + i;
            int r = idx >> 3;
            int c4 = idx & 7;
            float4 f = *reinterpret_cast<const float4*>(&A[(size_t)(m0 + r)*K + k0 + c4*2]);
            As[c4*2  ][r] = make_float2(tf32f(f.x), tf32f(f.y));
            As[c4*2+1][r] = make_float2(tf32f(f.z), tf32f(f.w));
        }
#pragma unroll
        for (int i = 0; i < 2; i++) {           // B tile 16x64 complex
            int idx = tid + i*256;
            int r = idx >> 5;
            int c4 = idx & 31;
            float4 f = *reinterpret_cast<const float4*>(&W[(size_t)(k0 + r)*NC + n0 + c4*2]);
            *reinterpret_cast<float4*>(&Bs[r][c4*2]) =
                make_float4(tf32f(f.x), tf32f(f.y), tf32f(f.z), tf32f(f.w));
        }
        __syncthreads();

#pragma unroll
        for (int ks = 0; ks < TBK; ks += 8) {
            uint32_t ar[2][4], ai[2][4], nai[2][4];
            uint32_t br[4][2], bi[4][2];
#pragma unroll
            for (int mt = 0; mt < 2; mt++) {
                int mb = warp_m*32 + mt*16;
                float2 q0 = As[ks+tg  ][mb + g    ];
                float2 q1 = As[ks+tg  ][mb + g + 8];
                float2 q2 = As[ks+tg+4][mb + g    ];
                float2 q3 = As[ks+tg+4][mb + g + 8];
                ar[mt][0] = __float_as_uint(q0.x); ai[mt][0] = __float_as_uint(q0.y);
                ar[mt][1] = __float_as_uint(q1.x); ai[mt][1] = __float_as_uint(q1.y);
                ar[mt][2] = __float_as_uint(q2.x); ai[mt][2] = __float_as_uint(q2.y);
                ar[mt][3] = __float_as_uint(q3.x); ai[mt][3] = __float_as_uint(q3.y);
#pragma unroll
                for (int t = 0; t < 4; t++) nai[mt][t] = ai[mt][t] ^ 0x80000000u;
            }
#pragma unroll
            for (int nt = 0; nt < 4; nt++) {
                int nb = warp_n*32 + nt*8;
                float2 w0 = Bs[ks+tg  ][nb + g];
                float2 w1 = Bs[ks+tg+4][nb + g];
                br[nt][0] = __float_as_uint(w0.x); bi[nt][0] = __float_as_uint(w0.y);
                br[nt][1] = __float_as_uint(w1.x); bi[nt][1] = __float_as_uint(w1.y);
            }
#pragma unroll
            for (int mt = 0; mt < 2; mt++)
#pragma unroll
                for (int nt = 0; nt < 4; nt++) {
                    mma_tf32(cr[mt][nt], ar[mt],  br[nt]);
                    mma_tf32(cr[mt][nt], nai[mt], bi[nt]);
                    mma_tf32(ci[mt][nt], ar[mt],  bi[nt]);
                    mma_tf32(ci[mt][nt], ai[mt],  br[nt]);
                }
        }
        __syncthreads();
    }

#pragma unroll
    for (int mt = 0; mt < 2; mt++)
#pragma unroll
        for (int nt = 0; nt < 4; nt++)
#pragma unroll
            for (int c = 0; c < 4; c++) {
                int row = m0 + warp_m*32 + mt*16 + g + ((c >= 2) ? 8 : 0);
                int col = n0 + warp_n*32 + nt*8 + 2*tg + (c & 1);
                epilog(C, NC, row, col, cr[mt][nt][c], ci[mt][nt][c], epi, bias, modb);
            }
}

// ---------------- tensor-core attention -------------------------------------
// grid (bh=16, qtile=16, variant=4), block 256 (8 warps).
// S = Q·K^T via mma (warp tile 16x16), P=exp(S*scale) (no max; scores bounded),
// rowsum via quad shuffles, PV via mma (warp tile 16x32).
#define ATQ 64
#define ATK 32
#define QS_S 72
#define KS_S 72
#define VS_S 72
#define PS_S 40

__global__ __launch_bounds__(256) void ct_attention_tc(float* __restrict__ planes) {
    __shared__ float Qs[ATQ][QS_S];    // [m][k] tf32
    __shared__ float Ks[ATK][KS_S];    // [n][k] tf32 (B col-major)
    __shared__ float Vs[ATK][VS_S];    // [k][n] tf32
    __shared__ float Ps[ATQ][PS_S];    // [m][k'] tf32
    __shared__ float red[ATQ][2];
    __shared__ float lsum[ATQ];

    int bh = blockIdx.x;
    int b  = bh >> 3;
    int h  = bh & 7;
    int q0 = blockIdx.y * ATQ;
    int v  = blockIdx.z;
    int tid  = threadIdx.x;
    int warp = tid >> 5;
    int lane = tid & 31;
    int g  = lane >> 2;
    int tg = lane & 3;
    int warp_m = warp >> 1;     // 0..3
    int warp_n = warp & 1;      // 0..1
    int sm0 = warp_m * 16;

    for (int e = tid; e < ATQ*DHH; e += 256) {
        int i = e >> 6, d = e & 63;
        float2 c = g_q[(size_t)(b*NN + q0 + i)*INNERC + h*DHH + d];
        Qs[i][d] = tf32f((v < 2) ? c.x : c.y);
    }
    if (tid < ATQ) lsum[tid] = 0.f;

    float o[4][4] = {};
    __syncthreads();

    for (int kt = 0; kt < NN; kt += ATK) {
        for (int e = tid; e < ATK*DHH; e += 256) {
            int j = e >> 6, d = e & 63;
            const float2* base = &g_kv[(size_t)(b*NN + kt + j)*2*INNERC + h*DHH + d];
            float2 kc = base[0];
            float2 vc = base[INNERC];
            Ks[j][d] = tf32f((v & 1) ? -kc.y : kc.x);
            Vs[j][d] = tf32f((v < 2) ? vc.x : vc.y);
        }
        __syncthreads();

        // ---- S = Q K^T : warp rows sm0..+16, cols warp_n*16..+16 ----
        float sacc[2][4] = {};
#pragma unroll
        for (int ks = 0; ks < DHH; ks += 8) {
            uint32_t a[4];
            a[0] = __float_as_uint(Qs[sm0 + g    ][ks + tg    ]);
            a[1] = __float_as_uint(Qs[sm0 + g + 8][ks + tg    ]);
            a[2] = __float_as_uint(Qs[sm0 + g    ][ks + tg + 4]);
            a[3] = __float_as_uint(Qs[sm0 + g + 8][ks + tg + 4]);
#pragma unroll
            for (int nt = 0; nt < 2; nt++) {
                int nb = warp_n*16 + nt*8;
                uint32_t bb[2];
                bb[0] = __float_as_uint(Ks[nb + g][ks + tg    ]);
                bb[1] = __float_as_uint(Ks[nb + g][ks + tg + 4]);
                mma_tf32(sacc[nt], a, bb);
            }
        }

        // ---- exp, store P (tf32), rowsums ----
        float lo = 0.f, hi = 0.f;
#pragma unroll
        for (int nt = 0; nt < 2; nt++) {
            int cb = warp_n*16 + nt*8 + 2*tg;
#pragma unroll
            for (int c = 0; c < 4; c++) {
                float p = __expf(sacc[nt][c] * ATT_SCALE);
                p = tf32f(p);
                int row = sm0 + g + ((c >= 2) ? 8 : 0);
                Ps[row][cb + (c & 1)] = p;
                if (c < 2) lo += p; else hi += p;
            }
        }
#pragma unroll
        for (int off = 1; off <= 2; off <<= 1) {
            lo += __shfl_xor_sync(0xffffffffu, lo, off);
            hi += __shfl_xor_sync(0xffffffffu, hi, off);
        }
        if (tg == 0) {
            red[sm0 + g    ][warp_n] = lo;
            red[sm0 + g + 8][warp_n] = hi;
        }
        __syncthreads();
        if (tid < ATQ) lsum[tid] += red[tid][0] + red[tid][1];

        // ---- O += P V : warp rows sm0..+16, cols warp_n*32..+32 ----
#pragma unroll
        for (int k8 = 0; k8 < ATK; k8 += 8) {
            uint32_t a[4];
            a[0] = __float_as_uint(Ps[sm0 + g    ][k8 + tg    ]);
            a[1] = __float_as_uint(Ps[sm0 + g + 8][k8 + tg    ]);
            a[2] = __float_as_uint(Ps[sm0 + g    ][k8 + tg + 4]);
            a[3] = __float_as_uint(Ps[sm0 + g + 8][k8 + tg + 4]);
#pragma unroll
            for (int nt = 0; nt < 4; nt++) {
                int nb = warp_n*32 + nt*8;
                uint32_t bb[2];
                bb[0] = __float_as_uint(Vs[k8 + tg    ][nb + g]);
                bb[1] = __float_as_uint(Vs[k8 + tg + 4][nb + g]);
                mma_tf32(o[nt], a, bb);
            }
        }
        __syncthreads();
    }

    float inv_lo = 1.f / lsum[sm0 + g];
    float inv_hi = 1.f / lsum[sm0 + g + 8];
    float* outp = planes + (size_t)v * MM * INNERC;
#pragma unroll
    for (int nt = 0; nt < 4; nt++) {
        int cb = warp_n*32 + nt*8 + 2*tg;
#pragma unroll
        for (int c = 0; c < 4; c++) {
            int row = sm0 + g + ((c >= 2) ? 8 : 0);
            float inv = (c >= 2) ? inv_hi : inv_lo;
            outp[(size_t)(b*NN + q0 + row)*INNERC + h*DHH + cb + (c & 1)] = o[nt][c] * inv;
        }
    }
}

// combine 4 variant planes: re = o0 - o3, im = o1 + o2  (2 elems/thread)
__global__ __launch_bounds__(256) void ct_combine(const float* __restrict__ planes) {
    int e = blockIdx.x*blockDim.x + threadIdx.x;
    if (e >= MM*INNERC/2) return;
    const size_t P = (size_t)MM * INNERC;
    const float2* p0 = reinterpret_cast<const float2*>(planes);
    const float2* p1 = reinterpret_cast<const float2*>(planes + P);
    const float2* p2 = reinterpret_cast<const float2*>(planes + 2*P);
    const float2* p3 = reinterpret_cast<const float2*>(planes + 3*P);
    float2 a = p0[e], bq = p1[e], c = p2[e], d = p3[e];
    float4 out = make_float4(a.x - d.x, bq.x + c.x, a.y - d.y, bq.y + c.y);
    *reinterpret_cast<float4*>(&g_o[2*e]) = out;
}

// ---------------- launcher ----------------
extern "C" void kernel_launch(void* const* d_in, const int* in_sizes, int n_in,
                              void* d_out, int out_size) {
    (void)in_sizes; (void)n_in; (void)out_size;
    const float2* x          = (const float2*)d_in[0];
    const float2* gamma_attn = (const float2*)d_in[1];
    const float2* Wq         = (const float2*)d_in[2];
    const float2* Wkv        = (const float2*)d_in[3];
    const float2* Wo         = (const float2*)d_in[4];
    const float2* gamma_ff   = (const float2*)d_in[5];
    const float2* W1         = (const float2*)d_in[6];
    const float2* b1         = (const float2*)d_in[7];
    const float*  modb       = (const float*)d_in[8];
    const float2* W2         = (const float2*)d_in[9];
    const float2* b2         = (const float2*)d_in[10];
    const float2* gfin       = (const float2*)d_in[11];

    float2 *px, *phn, *pq, *pkv, *po, *pff;
    cudaGetSymbolAddress((void**)&px,  g_x);
    cudaGetSymbolAddress((void**)&phn, g_hn);
    cudaGetSymbolAddress((void**)&pq,  g_q);
    cudaGetSymbolAddress((void**)&pkv, g_kv);
    cudaGetSymbolAddress((void**)&po,  g_o);
    cudaGetSymbolAddress((void**)&pff, g_ff);
    float* planes = (float*)pff;

    cudaMemcpyAsync(px, x, sizeof(float2)*MM*DIMC, cudaMemcpyDeviceToDevice);
    ct_rope_init<<<(NN*DHH + 255)/256, 256>>>();

    for (int l = 0; l < NDEPTH; l++) {
        ct_rmsnorm<<<MM, 128>>>(px, gamma_attn + l*DIMC, phn);
        ct_cgemm_tc<<<dim3(INNERC/TBN,   MM/TBM), 256>>>(phn, Wq  + (size_t)l*DIMC*INNERC,   pq,  DIMC, INNERC,   0, nullptr, nullptr);
        ct_cgemm_tc<<<dim3(2*INNERC/TBN, MM/TBM), 256>>>(phn, Wkv + (size_t)l*DIMC*2*INNERC, pkv, DIMC, 2*INNERC, 1, nullptr, nullptr);
        ct_attention_tc<<<dim3(BB*NHEADS, NN/ATQ, 4), 256>>>(planes);
        ct_combine<<<(MM*INNERC/2 + 255)/256, 256>>>(planes);
        ct_cgemm_tc<<<dim3(DIMC/TBN, MM/TBM), 256>>>(po, Wo + (size_t)l*INNERC*DIMC, px, INNERC, DIMC, 2, nullptr, nullptr);
        ct_rmsnorm<<<MM, 128>>>(px, gamma_ff + l*DIMC, phn);
        ct_cgemm_tc<<<dim3(FFC/TBN,  MM/TBM), 256>>>(phn, W1 + (size_t)l*DIMC*FFC, pff, DIMC, FFC, 3, b1 + l*FFC,  modb + l);
        ct_cgemm_tc<<<dim3(DIMC/TBN, MM/TBM), 256>>>(pff, W2 + (size_t)l*FFC*DIMC, px,  FFC,  DIMC, 4, b2 + l*DIMC, nullptr);
    }
    ct_rmsnorm<<<MM, 128>>>(px, gfin, (float2*)d_out);
}

// round 6
// speedup vs baseline: 3.9198x; 1.1004x over previous
#include <cuda_runtime.h>
#include <math.h>
#include <stdint.h>

#define BB     2
#define NN     1024
#define DIMC   512
#define NHEADS 8
#define DHH    64
#define INNERC 512
#define FFC    2048
#define NDEPTH 2
#define MM     (BB*NN)
#define EPSF   1e-6f
#define ATT_SCALE 0.125f

// ---------------- scratch ----------------
__device__ float2 g_x [MM*DIMC];
__device__ float2 g_hn[MM*DIMC];
__device__ float2 g_q [MM*INNERC];
__device__ float2 g_kv[MM*2*INNERC];
__device__ float2 g_o [MM*INNERC];
__device__ float2 g_ff[MM*FFC];       // FF intermediate / attention variant planes
__device__ float2 g_rope[NN*DHH];

__device__ __forceinline__ float2 cmulf(float2 a, float2 b) {
    return make_float2(a.x*b.x - a.y*b.y, a.x*b.y + a.y*b.x);
}
__device__ __forceinline__ uint32_t f2tf32(float x) {
    uint32_t u;
    asm("cvt.rna.tf32.f32 %0, %1;" : "=r"(u) : "f"(x));
    return u;
}
__device__ __forceinline__ float tf32f(float x) {
    return __uint_as_float(f2tf32(x));
}
__device__ __forceinline__ void mma_tf32(float* d, const uint32_t* a, const uint32_t* b) {
    asm volatile(
        "mma.sync.aligned.m16n8k8.row.col.f32.tf32.tf32.f32 "
        "{%0,%1,%2,%3},{%4,%5,%6,%7},{%8,%9},{%0,%1,%2,%3};"
        : "+f"(d[0]), "+f"(d[1]), "+f"(d[2]), "+f"(d[3])
        : "r"(a[0]), "r"(a[1]), "r"(a[2]), "r"(a[3]), "r"(b[0]), "r"(b[1]));
}

// ---------------- rope table ----------------
__global__ void ct_rope_init() {
    int i = blockIdx.x*blockDim.x + threadIdx.x;
    if (i >= NN*DHH) return;
    int n = i / DHH, d = i % DHH;
    double inv = exp(-((double)d / (double)DHH) * log(10000.0));
    double fr  = (double)n * inv;
    g_rope[i] = make_float2((float)cos(fr), (float)sin(fr));
}

// ---------------- complex rmsnorm ----------------
__global__ __launch_bounds__(128) void ct_rmsnorm(const float2* __restrict__ in,
                                                  const float2* __restrict__ gamma,
                                                  float2* __restrict__ out) {
    int row = blockIdx.x;
    const float2* xr = in + row*DIMC;
    float ss = 0.f;
    for (int d = threadIdx.x; d < DIMC; d += 128) {
        float2 v = xr[d];
        ss = fmaf(v.x, v.x, ss);
        ss = fmaf(v.y, v.y, ss);
    }
#pragma unroll
    for (int off = 16; off; off >>= 1) ss += __shfl_xor_sync(0xffffffffu, ss, off);
    __shared__ float sred[4];
    if ((threadIdx.x & 31) == 0) sred[threadIdx.x >> 5] = ss;
    __syncthreads();
    ss = sred[0] + sred[1] + sred[2] + sred[3];
    float sc = rsqrtf(ss * (1.f/(float)DIMC) + EPSF);
    for (int d = threadIdx.x; d < DIMC; d += 128) {
        float2 v = xr[d];
        float2 g = gamma[d];
        out[row*DIMC + d] = make_float2(sc*(v.x*g.x - v.y*g.y),
                                        sc*(v.x*g.y + v.y*g.x));
    }
}

// ---------------- tf32 tensor-core complex GEMM (float2 smem planes) ---------
#define TBM 128
#define TBN 64
#define TBK 16
#define APAD2 132   // float2 stride; ≡4 mod 16 → conflict-free LDS.64 frag reads
#define BPAD2 68

__device__ __forceinline__ void epilog(float2* __restrict__ C, int NC, int m, int n,
                                       float re, float im, int epi,
                                       const float2* __restrict__ bias,
                                       const float* __restrict__ modb) {
    int idx = m*NC + n;
    float2 r = make_float2(re, im);
    if (epi == 0) {
        float2 ph = g_rope[(m & (NN-1))*DHH + (n & (DHH-1))];
        C[idx] = cmulf(r, ph);
    } else if (epi == 1) {
        if (n < INNERC) {
            float2 ph = g_rope[(m & (NN-1))*DHH + (n & (DHH-1))];
            r = cmulf(r, ph);
        }
        C[idx] = r;
    } else if (epi == 2) {
        float2 c = C[idx];
        C[idx] = make_float2(c.x + r.x, c.y + r.y);
    } else if (epi == 3) {
        float2 bv = bias[n];
        r.x += bv.x; r.y += bv.y;
        float mag = sqrtf(r.x*r.x + r.y*r.y);
        float t = fmaxf(mag + *modb, 0.f);
        float cl = t*t;
        if (mag > 0.f) {
            float s = cl / mag;
            r.x *= s; r.y *= s;
        } else {
            r.x = cl; r.y = 0.f;
        }
        C[idx] = r;
    } else {
        float2 bv = bias[n];
        float2 c = C[idx];
        C[idx] = make_float2(c.x + r.x + bv.x, c.y + r.y + bv.y);
    }
}

__global__ __launch_bounds__(256, 2) void ct_cgemm_tc(const float2* __restrict__ A,
                                                      const float2* __restrict__ W,
                                                      float2* __restrict__ C,
                                                      int K, int NC, int epi,
                                                      const float2* __restrict__ bias,
                                                      const float* __restrict__ modb) {
    __shared__ float2 As[TBK][APAD2];   // (re,im) interleaved, [k][m]
    __shared__ float2 Bs[TBK][BPAD2];   // [k][n]

    int tid  = threadIdx.x;
    int warp = tid >> 5;
    int lane = tid & 31;
    int g    = lane >> 2;
    int tg   = lane & 3;
    int warp_m = warp & 3;
    int warp_n = warp >> 2;
    int m0 = blockIdx.y * TBM;
    int n0 = blockIdx.x * TBN;

    float cr[2][4][4] = {};
    float ci[2][4][4] = {};

    for (int k0 = 0; k0 < K; k0 += TBK) {
#pragma unroll
        for (int i = 0; i < 4; i++) {           // A tile 128x16 complex
            int idx = tid*4 + i;
            int r = idx >> 3;
            int c4 = idx & 7;
            float4 f = *reinterpret_cast<const float4*>(&A[(size_t)(m0 + r)*K + k0 + c4*2]);
            As[c4*2  ][r] = make_float2(tf32f(f.x), tf32f(f.y));
            As[c4*2+1][r] = make_float2(tf32f(f.z), tf32f(f.w));
        }
#pragma unroll
        for (int i = 0; i < 2; i++) {           // B tile 16x64 complex
            int idx = tid + i*256;
            int r = idx >> 5;
            int c4 = idx & 31;
            float4 f = *reinterpret_cast<const float4*>(&W[(size_t)(k0 + r)*NC + n0 + c4*2]);
            *reinterpret_cast<float4*>(&Bs[r][c4*2]) =
                make_float4(tf32f(f.x), tf32f(f.y), tf32f(f.z), tf32f(f.w));
        }
        __syncthreads();

#pragma unroll
        for (int ks = 0; ks < TBK; ks += 8) {
            uint32_t ar[2][4], ai[2][4], nai[2][4];
            uint32_t br[4][2], bi[4][2];
#pragma unroll
            for (int mt = 0; mt < 2; mt++) {
                int mb = warp_m*32 + mt*16;
                float2 q0 = As[ks+tg  ][mb + g    ];
                float2 q1 = As[ks+tg  ][mb + g + 8];
                float2 q2 = As[ks+tg+4][mb + g    ];
                float2 q3 = As[ks+tg+4][mb + g + 8];
                ar[mt][0] = __float_as_uint(q0.x); ai[mt][0] = __float_as_uint(q0.y);
                ar[mt][1] = __float_as_uint(q1.x); ai[mt][1] = __float_as_uint(q1.y);
                ar[mt][2] = __float_as_uint(q2.x); ai[mt][2] = __float_as_uint(q2.y);
                ar[mt][3] = __float_as_uint(q3.x); ai[mt][3] = __float_as_uint(q3.y);
#pragma unroll
                for (int t = 0; t < 4; t++) nai[mt][t] = ai[mt][t] ^ 0x80000000u;
            }
#pragma unroll
            for (int nt = 0; nt < 4; nt++) {
                int nb = warp_n*32 + nt*8;
                float2 w0 = Bs[ks+tg  ][nb + g];
                float2 w1 = Bs[ks+tg+4][nb + g];
                br[nt][0] = __float_as_uint(w0.x); bi[nt][0] = __float_as_uint(w0.y);
                br[nt][1] = __float_as_uint(w1.x); bi[nt][1] = __float_as_uint(w1.y);
            }
#pragma unroll
            for (int mt = 0; mt < 2; mt++)
#pragma unroll
                for (int nt = 0; nt < 4; nt++) {
                    mma_tf32(cr[mt][nt], ar[mt],  br[nt]);
                    mma_tf32(cr[mt][nt], nai[mt], bi[nt]);
                    mma_tf32(ci[mt][nt], ar[mt],  bi[nt]);
                    mma_tf32(ci[mt][nt], ai[mt],  br[nt]);
                }
        }
        __syncthreads();
    }

#pragma unroll
    for (int mt = 0; mt < 2; mt++)
#pragma unroll
        for (int nt = 0; nt < 4; nt++)
#pragma unroll
            for (int c = 0; c < 4; c++) {
                int row = m0 + warp_m*32 + mt*16 + g + ((c >= 2) ? 8 : 0);
                int col = n0 + warp_n*32 + nt*8 + 2*tg + (c & 1);
                epilog(C, NC, row, col, cr[mt][nt][c], ci[mt][nt][c], epi, bias, modb);
            }
}

// ---------------- tensor-core attention -------------------------------------
// grid (bh=16, qtile=16, variant=4), block 256 (8 warps).
// S = Q·K^T via mma (warp tile 16x16), P=exp(S*scale) (no max; scores bounded),
// rowsum via quad shuffles, PV via mma (warp tile 16x32).
#define ATQ 64
#define ATK 32
#define QS_S 72
#define KS_S 72
#define VS_S 72
#define PS_S 40

__global__ __launch_bounds__(256) void ct_attention_tc(float* __restrict__ planes) {
    __shared__ float Qs[ATQ][QS_S];    // [m][k] tf32
    __shared__ float Ks[ATK][KS_S];    // [n][k] tf32 (B col-major)
    __shared__ float Vs[ATK][VS_S];    // [k][n] tf32
    __shared__ float Ps[ATQ][PS_S];    // [m][k'] tf32
    __shared__ float red[ATQ][2];
    __shared__ float lsum[ATQ];

    int bh = blockIdx.x;
    int b  = bh >> 3;
    int h  = bh & 7;
    int q0 = blockIdx.y * ATQ;
    int v  = blockIdx.z;
    int tid  = threadIdx.x;
    int warp = tid >> 5;
    int lane = tid & 31;
    int g  = lane >> 2;
    int tg = lane & 3;
    int warp_m = warp >> 1;     // 0..3
    int warp_n = warp & 1;      // 0..1
    int sm0 = warp_m * 16;

    for (int e = tid; e < ATQ*DHH; e += 256) {
        int i = e >> 6, d = e & 63;
        float2 c = g_q[(size_t)(b*NN + q0 + i)*INNERC + h*DHH + d];
        Qs[i][d] = tf32f((v < 2) ? c.x : c.y);
    }
    if (tid < ATQ) lsum[tid] = 0.f;

    float o[4][4] = {};
    __syncthreads();

    for (int kt = 0; kt < NN; kt += ATK) {
        for (int e = tid; e < ATK*DHH; e += 256) {
            int j = e >> 6, d = e & 63;
            const float2* base = &g_kv[(size_t)(b*NN + kt + j)*2*INNERC + h*DHH + d];
            float2 kc = base[0];
            float2 vc = base[INNERC];
            Ks[j][d] = tf32f((v & 1) ? -kc.y : kc.x);
            Vs[j][d] = tf32f((v < 2) ? vc.x : vc.y);
        }
        __syncthreads();

        // ---- S = Q K^T : warp rows sm0..+16, cols warp_n*16..+16 ----
        float sacc[2][4] = {};
#pragma unroll
        for (int ks = 0; ks < DHH; ks += 8) {
            uint32_t a[4];
            a[0] = __float_as_uint(Qs[sm0 + g    ][ks + tg    ]);
            a[1] = __float_as_uint(Qs[sm0 + g + 8][ks + tg    ]);
            a[2] = __float_as_uint(Qs[sm0 + g    ][ks + tg + 4]);
            a[3] = __float_as_uint(Qs[sm0 + g + 8][ks + tg + 4]);
#pragma unroll
            for (int nt = 0; nt < 2; nt++) {
                int nb = warp_n*16 + nt*8;
                uint32_t bb[2];
                bb[0] = __float_as_uint(Ks[nb + g][ks + tg    ]);
                bb[1] = __float_as_uint(Ks[nb + g][ks + tg + 4]);
                mma_tf32(sacc[nt], a, bb);
            }
        }

        // ---- exp, store P (tf32), rowsums ----
        float lo = 0.f, hi = 0.f;
#pragma unroll
        for (int nt = 0; nt < 2; nt++) {
            int cb = warp_n*16 + nt*8 + 2*tg;
#pragma unroll
            for (int c = 0; c < 4; c++) {
                float p = __expf(sacc[nt][c] * ATT_SCALE);
                p = tf32f(p);
                int row = sm0 + g + ((c >= 2) ? 8 : 0);
                Ps[row][cb + (c & 1)] = p;
                if (c < 2) lo += p; else hi += p;
            }
        }
#pragma unroll
        for (int off = 1; off <= 2; off <<= 1) {
            lo += __shfl_xor_sync(0xffffffffu, lo, off);
            hi += __shfl_xor_sync(0xffffffffu, hi, off);
        }
        if (tg == 0) {
            red[sm0 + g    ][warp_n] = lo;
            red[sm0 + g + 8][warp_n] = hi;
        }
        __syncthreads();
        if (tid < ATQ) lsum[tid] += red[tid][0] + red[tid][1];

        // ---- O += P V : warp rows sm0..+16, cols warp_n*32..+32 ----
#pragma unroll
        for (int k8 = 0; k8 < ATK; k8 += 8) {
            uint32_t a[4];
            a[0] = __float_as_uint(Ps[sm0 + g    ][k8 + tg    ]);
            a[1] = __float_as_uint(Ps[sm0 + g + 8][k8 + tg    ]);
            a[2] = __float_as_uint(Ps[sm0 + g    ][k8 + tg + 4]);
            a[3] = __float_as_uint(Ps[sm0 + g + 8][k8 + tg + 4]);
#pragma unroll
            for (int nt = 0; nt < 4; nt++) {
                int nb = warp_n*32 + nt*8;
                uint32_t bb[2];
                bb[0] = __float_as_uint(Vs[k8 + tg    ][nb + g]);
                bb[1] = __float_as_uint(Vs[k8 + tg + 4][nb + g]);
                mma_tf32(o[nt], a, bb);
            }
        }
        __syncthreads();
    }

    float inv_lo = 1.f / lsum[sm0 + g];
    float inv_hi = 1.f / lsum[sm0 + g + 8];
    float* outp = planes + (size_t)v * MM * INNERC;
#pragma unroll
    for (int nt = 0; nt < 4; nt++) {
        int cb = warp_n*32 + nt*8 + 2*tg;
#pragma unroll
        for (int c = 0; c < 4; c++) {
            int row = sm0 + g + ((c >= 2) ? 8 : 0);
            float inv = (c >= 2) ? inv_hi : inv_lo;
            outp[(size_t)(b*NN + q0 + row)*INNERC + h*DHH + cb + (c & 1)] = o[nt][c] * inv;
        }
    }
}

// combine 4 variant planes: re = o0 - o3, im = o1 + o2  (2 elems/thread)
__global__ __launch_bounds__(256) void ct_combine(const float* __restrict__ planes) {
    int e = blockIdx.x*blockDim.x + threadIdx.x;
    if (e >= MM*INNERC/2) return;
    const size_t P = (size_t)MM * INNERC;
    const float2* p0 = reinterpret_cast<const float2*>(planes);
    const float2* p1 = reinterpret_cast<const float2*>(planes + P);
    const float2* p2 = reinterpret_cast<const float2*>(planes + 2*P);
    const float2* p3 = reinterpret_cast<const float2*>(planes + 3*P);
    float2 a = p0[e], bq = p1[e], c = p2[e], d = p3[e];
    float4 out = make_float4(a.x - d.x, bq.x + c.x, a.y - d.y, bq.y + c.y);
    *reinterpret_cast<float4*>(&g_o[2*e]) = out;
}

// ---------------- launcher ----------------
extern "C" void kernel_launch(void* const* d_in, const int* in_sizes, int n_in,
                              void* d_out, int out_size) {
    (void)in_sizes; (void)n_in; (void)out_size;
    const float2* x          = (const float2*)d_in[0];
    const float2* gamma_attn = (const float2*)d_in[1];
    const float2* Wq         = (const float2*)d_in[2];
    const float2* Wkv        = (const float2*)d_in[3];
    const float2* Wo         = (const float2*)d_in[4];
    const float2* gamma_ff   = (const float2*)d_in[5];
    const float2* W1         = (const float2*)d_in[6];
    const float2* b1         = (const float2*)d_in[7];
    const float*  modb       = (const float*)d_in[8];
    const float2* W2         = (const float2*)d_in[9];
    const float2* b2         = (const float2*)d_in[10];
    const float2* gfin       = (const float2*)d_in[11];

    float2 *px, *phn, *pq, *pkv, *po, *pff;
    cudaGetSymbolAddress((void**)&px,  g_x);
    cudaGetSymbolAddress((void**)&phn, g_hn);
    cudaGetSymbolAddress((void**)&pq,  g_q);
    cudaGetSymbolAddress((void**)&pkv, g_kv);
    cudaGetSymbolAddress((void**)&po,  g_o);
    cudaGetSymbolAddress((void**)&pff, g_ff);
    float* planes = (float*)pff;

    cudaMemcpyAsync(px, x, sizeof(float2)*MM*DIMC, cudaMemcpyDeviceToDevice);
    ct_rope_init<<<(NN*DHH + 255)/256, 256>>>();

    for (int l = 0; l < NDEPTH; l++) {
        ct_rmsnorm<<<MM, 128>>>(px, gamma_attn + l*DIMC, phn);
        ct_cgemm_tc<<<dim3(INNERC/TBN,   MM/TBM), 256>>>(phn, Wq  + (size_t)l*DIMC*INNERC,   pq,  DIMC, INNERC,   0, nullptr, nullptr);
        ct_cgemm_tc<<<dim3(2*INNERC/TBN, MM/TBM), 256>>>(phn, Wkv + (size_t)l*DIMC*2*INNERC, pkv, DIMC, 2*INNERC, 1, nullptr, nullptr);
        ct_attention_tc<<<dim3(BB*NHEADS, NN/ATQ, 4), 256>>>(planes);
        ct_combine<<<(MM*INNERC/2 + 255)/256, 256>>>(planes);
        ct_cgemm_tc<<<dim3(DIMC/TBN, MM/TBM), 256>>>(po, Wo + (size_t)l*INNERC*DIMC, px, INNERC, DIMC, 2, nullptr, nullptr);
        ct_rmsnorm<<<MM, 128>>>(px, gamma_ff + l*DIMC, phn);
        ct_cgemm_tc<<<dim3(FFC/TBN,  MM/TBM), 256>>>(phn, W1 + (size_t)l*DIMC*FFC, pff, DIMC, FFC, 3, b1 + l*FFC,  modb + l);
        ct_cgemm_tc<<<dim3(DIMC/TBN, MM/TBM), 256>>>(pff, W2 + (size_t)l*FFC*DIMC, px,  FFC,  DIMC, 4, b2 + l*DIMC, nullptr);
    }
    ct_rmsnorm<<<MM, 128>>>(px, gfin, (float2*)d_out);
}

// round 7
// speedup vs baseline: 4.1930x; 1.0697x over previous
#include <cuda_runtime.h>
#include <math.h>
#include <stdint.h>

#define BB     2
#define NN     1024
#define DIMC   512
#define NHEADS 8
#define DHH    64
#define INNERC 512
#define FFC    2048
#define NDEPTH 2
#define MM     (BB*NN)
#define EPSF   1e-6f
#define ATT_SCALE 0.125f

// ---------------- scratch ----------------
__device__ float2 g_x [MM*DIMC];
__device__ float2 g_hn[MM*DIMC];
__device__ float2 g_q [MM*INNERC];
__device__ float2 g_kv[MM*2*INNERC];
__device__ float2 g_o [MM*INNERC];
__device__ float2 g_ff[MM*FFC];       // FF intermediate
__device__ float2 g_rope[NN*DHH];

__device__ __forceinline__ float2 cmulf(float2 a, float2 b) {
    return make_float2(a.x*b.x - a.y*b.y, a.x*b.y + a.y*b.x);
}
__device__ __forceinline__ uint32_t f2tf32(float x) {
    uint32_t u;
    asm("cvt.rna.tf32.f32 %0, %1;" : "=r"(u) : "f"(x));
    return u;
}
__device__ __forceinline__ float tf32f(float x) {
    return __uint_as_float(f2tf32(x));
}
__device__ __forceinline__ void mma_tf32(float* d, const uint32_t* a, const uint32_t* b) {
    asm volatile(
        "mma.sync.aligned.m16n8k8.row.col.f32.tf32.tf32.f32 "
        "{%0,%1,%2,%3},{%4,%5,%6,%7},{%8,%9},{%0,%1,%2,%3};"
        : "+f"(d[0]), "+f"(d[1]), "+f"(d[2]), "+f"(d[3])
        : "r"(a[0]), "r"(a[1]), "r"(a[2]), "r"(a[3]), "r"(b[0]), "r"(b[1]));
}

// ---------------- rope table ----------------
__global__ void ct_rope_init() {
    int i = blockIdx.x*blockDim.x + threadIdx.x;
    if (i >= NN*DHH) return;
    int n = i / DHH, d = i % DHH;
    double inv = exp(-((double)d / (double)DHH) * log(10000.0));
    double fr  = (double)n * inv;
    g_rope[i] = make_float2((float)cos(fr), (float)sin(fr));
}

// ---------------- complex rmsnorm ----------------
__global__ __launch_bounds__(128) void ct_rmsnorm(const float2* __restrict__ in,
                                                  const float2* __restrict__ gamma,
                                                  float2* __restrict__ out) {
    int row = blockIdx.x;
    const float2* xr = in + row*DIMC;
    float ss = 0.f;
    for (int d = threadIdx.x; d < DIMC; d += 128) {
        float2 v = xr[d];
        ss = fmaf(v.x, v.x, ss);
        ss = fmaf(v.y, v.y, ss);
    }
#pragma unroll
    for (int off = 16; off; off >>= 1) ss += __shfl_xor_sync(0xffffffffu, ss, off);
    __shared__ float sred[4];
    if ((threadIdx.x & 31) == 0) sred[threadIdx.x >> 5] = ss;
    __syncthreads();
    ss = sred[0] + sred[1] + sred[2] + sred[3];
    float sc = rsqrtf(ss * (1.f/(float)DIMC) + EPSF);
    for (int d = threadIdx.x; d < DIMC; d += 128) {
        float2 v = xr[d];
        float2 g = gamma[d];
        out[row*DIMC + d] = make_float2(sc*(v.x*g.x - v.y*g.y),
                                        sc*(v.x*g.y + v.y*g.x));
    }
}

// ---------------- tf32 tensor-core complex GEMM (float2 smem planes) ---------
#define TBM 128
#define TBN 64
#define TBK 16
#define APAD2 132
#define BPAD2 68

__device__ __forceinline__ void epilog(float2* __restrict__ C, int NC, int m, int n,
                                       float re, float im, int epi,
                                       const float2* __restrict__ bias,
                                       const float* __restrict__ modb) {
    int idx = m*NC + n;
    float2 r = make_float2(re, im);
    if (epi == 0) {
        float2 ph = g_rope[(m & (NN-1))*DHH + (n & (DHH-1))];
        C[idx] = cmulf(r, ph);
    } else if (epi == 1) {
        if (n < INNERC) {
            float2 ph = g_rope[(m & (NN-1))*DHH + (n & (DHH-1))];
            r = cmulf(r, ph);
        }
        C[idx] = r;
    } else if (epi == 2) {
        float2 c = C[idx];
        C[idx] = make_float2(c.x + r.x, c.y + r.y);
    } else if (epi == 3) {
        float2 bv = bias[n];
        r.x += bv.x; r.y += bv.y;
        float mag = sqrtf(r.x*r.x + r.y*r.y);
        float t = fmaxf(mag + *modb, 0.f);
        float cl = t*t;
        if (mag > 0.f) {
            float s = cl / mag;
            r.x *= s; r.y *= s;
        } else {
            r.x = cl; r.y = 0.f;
        }
        C[idx] = r;
    } else {
        float2 bv = bias[n];
        float2 c = C[idx];
        C[idx] = make_float2(c.x + r.x + bv.x, c.y + r.y + bv.y);
    }
}

__global__ __launch_bounds__(256, 2) void ct_cgemm_tc(const float2* __restrict__ A,
                                                      const float2* __restrict__ W,
                                                      float2* __restrict__ C,
                                                      int K, int NC, int epi,
                                                      const float2* __restrict__ bias,
                                                      const float* __restrict__ modb) {
    __shared__ float2 As[TBK][APAD2];
    __shared__ float2 Bs[TBK][BPAD2];

    int tid  = threadIdx.x;
    int warp = tid >> 5;
    int lane = tid & 31;
    int g    = lane >> 2;
    int tg   = lane & 3;
    int warp_m = warp & 3;
    int warp_n = warp >> 2;
    int m0 = blockIdx.y * TBM;
    int n0 = blockIdx.x * TBN;

    float cr[2][4][4] = {};
    float ci[2][4][4] = {};

    for (int k0 = 0; k0 < K; k0 += TBK) {
#pragma unroll
        for (int i = 0; i < 4; i++) {
            int idx = tid*4 + i;
            int r = idx >> 3;
            int c4 = idx & 7;
            float4 f = *reinterpret_cast<const float4*>(&A[(size_t)(m0 + r)*K + k0 + c4*2]);
            As[c4*2  ][r] = make_float2(tf32f(f.x), tf32f(f.y));
            As[c4*2+1][r] = make_float2(tf32f(f.z), tf32f(f.w));
        }
#pragma unroll
        for (int i = 0; i < 2; i++) {
            int idx = tid + i*256;
            int r = idx >> 5;
            int c4 = idx & 31;
            float4 f = *reinterpret_cast<const float4*>(&W[(size_t)(k0 + r)*NC + n0 + c4*2]);
            *reinterpret_cast<float4*>(&Bs[r][c4*2]) =
                make_float4(tf32f(f.x), tf32f(f.y), tf32f(f.z), tf32f(f.w));
        }
        __syncthreads();

#pragma unroll
        for (int ks = 0; ks < TBK; ks += 8) {
            uint32_t ar[2][4], ai[2][4], nai[2][4];
            uint32_t br[4][2], bi[4][2];
#pragma unroll
            for (int mt = 0; mt < 2; mt++) {
                int mb = warp_m*32 + mt*16;
                float2 q0 = As[ks+tg  ][mb + g    ];
                float2 q1 = As[ks+tg  ][mb + g + 8];
                float2 q2 = As[ks+tg+4][mb + g    ];
                float2 q3 = As[ks+tg+4][mb + g + 8];
                ar[mt][0] = __float_as_uint(q0.x); ai[mt][0] = __float_as_uint(q0.y);
                ar[mt][1] = __float_as_uint(q1.x); ai[mt][1] = __float_as_uint(q1.y);
                ar[mt][2] = __float_as_uint(q2.x); ai[mt][2] = __float_as_uint(q2.y);
                ar[mt][3] = __float_as_uint(q3.x); ai[mt][3] = __float_as_uint(q3.y);
#pragma unroll
                for (int t = 0; t < 4; t++) nai[mt][t] = ai[mt][t] ^ 0x80000000u;
            }
#pragma unroll
            for (int nt = 0; nt < 4; nt++) {
                int nb = warp_n*32 + nt*8;
                float2 w0 = Bs[ks+tg  ][nb + g];
                float2 w1 = Bs[ks+tg+4][nb + g];
                br[nt][0] = __float_as_uint(w0.x); bi[nt][0] = __float_as_uint(w0.y);
                br[nt][1] = __float_as_uint(w1.x); bi[nt][1] = __float_as_uint(w1.y);
            }
#pragma unroll
            for (int mt = 0; mt < 2; mt++)
#pragma unroll
                for (int nt = 0; nt < 4; nt++) {
                    mma_tf32(cr[mt][nt], ar[mt],  br[nt]);
                    mma_tf32(cr[mt][nt], nai[mt], bi[nt]);
                    mma_tf32(ci[mt][nt], ar[mt],  bi[nt]);
                    mma_tf32(ci[mt][nt], ai[mt],  br[nt]);
                }
        }
        __syncthreads();
    }

#pragma unroll
    for (int mt = 0; mt < 2; mt++)
#pragma unroll
        for (int nt = 0; nt < 4; nt++)
#pragma unroll
            for (int c = 0; c < 4; c++) {
                int row = m0 + warp_m*32 + mt*16 + g + ((c >= 2) ? 8 : 0);
                int col = n0 + warp_n*32 + nt*8 + 2*tg + (c & 1);
                epilog(C, NC, row, col, cr[mt][nt][c], ci[mt][nt][c], epi, bias, modb);
            }
}

// ---------------- merged-variant tensor-core attention ----------------------
// grid (bh=16, qtile=32), block 256 = 8 warps = (variant 0..3) x (q-half 0..1).
// K/V/Q staged ONCE per block as interleaved (re,im) float2; component select
// at fragment build. Per-warp private P region (no block sync between S and PV).
// Normalize + variant-combine fused in-kernel (writes g_o directly).
#define AQ2 32
#define AK2 16
#define KVP 68    // float2 row stride (≡4 mod 16 → conflict-free LDS.64 frags)
#define PST 20    // float row stride for P (≡4 mod 8 → conflict-free LDS.32)

__global__ __launch_bounds__(256, 2) void ct_attention_tc4() {
    __shared__ __align__(16) char smraw[34816];
    float2 (*Kc)[KVP] = reinterpret_cast<float2(*)[KVP]>(smraw);            //  8704 B
    float2 (*Vc)[KVP] = reinterpret_cast<float2(*)[KVP]>(smraw + 8704);     //  8704 B
    float2 (*Qc)[KVP] = reinterpret_cast<float2(*)[KVP]>(smraw + 17408);    // 17408 B
    float* Pbase  = reinterpret_cast<float*>(smraw + 17408);  // aliases Qc (dead after frag load)
    float* planes = reinterpret_cast<float*>(smraw);          // aliases all (dead after mainloop)

    int bh = blockIdx.x;
    int b  = bh >> 3;
    int h  = bh & 7;
    int q0 = blockIdx.y * AQ2;
    int tid = threadIdx.x, warp = tid >> 5, lane = tid & 31;
    int g = lane >> 2, tg = lane & 3;
    int v  = warp & 3;       // variant
    int qh = warp >> 2;      // q half
    int m0 = qh * 16;
    float* Ps = Pbase + warp * (16 * PST);

    // ---- stage Q once (tf32, interleaved) ----
#pragma unroll
    for (int i = 0; i < 4; i++) {
        int e = tid + i*256;
        int row = e >> 5, c4 = e & 31;
        float4 f = *reinterpret_cast<const float4*>(
            &g_q[(size_t)(b*NN + q0 + row)*INNERC + h*DHH + c4*2]);
        *reinterpret_cast<float4*>(&Qc[row][c4*2]) =
            make_float4(tf32f(f.x), tf32f(f.y), tf32f(f.z), tf32f(f.w));
    }
    __syncthreads();

    // ---- Q fragments in registers for the whole pass ----
    uint32_t qa[8][4];
#pragma unroll
    for (int ks = 0; ks < 8; ks++) {
        float2 c0 = Qc[m0 + g    ][ks*8 + tg];
        float2 c1 = Qc[m0 + g + 8][ks*8 + tg];
        float2 c2 = Qc[m0 + g    ][ks*8 + tg + 4];
        float2 c3 = Qc[m0 + g + 8][ks*8 + tg + 4];
        qa[ks][0] = __float_as_uint((v < 2) ? c0.x : c0.y);
        qa[ks][1] = __float_as_uint((v < 2) ? c1.x : c1.y);
        qa[ks][2] = __float_as_uint((v < 2) ? c2.x : c2.y);
        qa[ks][3] = __float_as_uint((v < 2) ? c3.x : c3.y);
    }

    float o[8][4] = {};
    float lsum_lo = 0.f, lsum_hi = 0.f;

    for (int kt = 0; kt < NN; kt += AK2) {
        __syncthreads();   // prev PV done (and Qc frag reads on first iter)
#pragma unroll
        for (int i = 0; i < 2; i++) {
            int e = tid + i*256;
            int row = e >> 5, c4 = e & 31;
            const float* src = reinterpret_cast<const float*>(
                &g_kv[(size_t)(b*NN + kt + row)*2*INNERC + h*DHH + c4*2]);
            float4 fk = *reinterpret_cast<const float4*>(src);
            float4 fv = *reinterpret_cast<const float4*>(src + 2*INNERC);
            *reinterpret_cast<float4*>(&Kc[row][c4*2]) =
                make_float4(tf32f(fk.x), tf32f(fk.y), tf32f(fk.z), tf32f(fk.w));
            *reinterpret_cast<float4*>(&Vc[row][c4*2]) =
                make_float4(tf32f(fv.x), tf32f(fv.y), tf32f(fv.z), tf32f(fv.w));
        }
        __syncthreads();

        // ---- S = q·k^T (m16 x n16 x k64) ----
        float sacc[2][4] = {};
#pragma unroll
        for (int ks = 0; ks < 8; ks++) {
#pragma unroll
            for (int nt = 0; nt < 2; nt++) {
                float2 k0 = Kc[nt*8 + g][ks*8 + tg];
                float2 k1 = Kc[nt*8 + g][ks*8 + tg + 4];
                uint32_t bb[2];
                bb[0] = __float_as_uint((v & 1) ? -k0.y : k0.x);
                bb[1] = __float_as_uint((v & 1) ? -k1.y : k1.x);
                mma_tf32(sacc[nt], qa[ks], bb);
            }
        }

        // ---- exp → per-warp P; register row-sum partials ----
#pragma unroll
        for (int nt = 0; nt < 2; nt++) {
            float p0 = tf32f(__expf(sacc[nt][0] * ATT_SCALE));
            float p1 = tf32f(__expf(sacc[nt][1] * ATT_SCALE));
            float p2 = tf32f(__expf(sacc[nt][2] * ATT_SCALE));
            float p3 = tf32f(__expf(sacc[nt][3] * ATT_SCALE));
            lsum_lo += p0 + p1;
            lsum_hi += p2 + p3;
            *reinterpret_cast<float2*>(&Ps[(g    )*PST + nt*8 + 2*tg]) = make_float2(p0, p1);
            *reinterpret_cast<float2*>(&Ps[(g + 8)*PST + nt*8 + 2*tg]) = make_float2(p2, p3);
        }
        __syncwarp();

        // ---- O += P·V (m16 x n64 x k16) ----
#pragma unroll
        for (int k8 = 0; k8 < AK2; k8 += 8) {
            uint32_t pa[4];
            pa[0] = __float_as_uint(Ps[(g    )*PST + k8 + tg    ]);
            pa[1] = __float_as_uint(Ps[(g + 8)*PST + k8 + tg    ]);
            pa[2] = __float_as_uint(Ps[(g    )*PST + k8 + tg + 4]);
            pa[3] = __float_as_uint(Ps[(g + 8)*PST + k8 + tg + 4]);
#pragma unroll
            for (int nt = 0; nt < 8; nt++) {
                float2 v0 = Vc[k8 + tg    ][nt*8 + g];
                float2 v1 = Vc[k8 + tg + 4][nt*8 + g];
                uint32_t bb[2];
                bb[0] = __float_as_uint((v < 2) ? v0.x : v0.y);
                bb[1] = __float_as_uint((v < 2) ? v1.x : v1.y);
                mma_tf32(o[nt], pa, bb);
            }
        }
    }
    __syncthreads();   // all smem dead; safe to reuse as output planes

    // ---- finalize row sums (quad shuffles), normalize, write variant planes ----
#pragma unroll
    for (int off = 1; off <= 2; off <<= 1) {
        lsum_lo += __shfl_xor_sync(0xffffffffu, lsum_lo, off);
        lsum_hi += __shfl_xor_sync(0xffffffffu, lsum_hi, off);
    }
    float inv_lo = 1.f / lsum_lo;
    float inv_hi = 1.f / lsum_hi;
    float* pl = planes + v * (AQ2 * DHH);
#pragma unroll
    for (int nt = 0; nt < 8; nt++) {
        int col = nt*8 + 2*tg;
        pl[(m0 + g    )*DHH + col    ] = o[nt][0] * inv_lo;
        pl[(m0 + g    )*DHH + col + 1] = o[nt][1] * inv_lo;
        pl[(m0 + g + 8)*DHH + col    ] = o[nt][2] * inv_hi;
        pl[(m0 + g + 8)*DHH + col + 1] = o[nt][3] * inv_hi;
    }
    __syncthreads();

    // ---- combine variants: re = o0 - o3, im = o1 + o2 → g_o ----
#pragma unroll
    for (int i = 0; i < 8; i++) {
        int e = tid + i*256;
        int row = e >> 6, d = e & 63;
        float re = planes[             row*DHH + d] - planes[3*AQ2*DHH + row*DHH + d];
        float im = planes[  AQ2*DHH + row*DHH + d] + planes[2*AQ2*DHH + row*DHH + d];
        g_o[(size_t)(b*NN + q0 + row)*INNERC + h*DHH + d] = make_float2(re, im);
    }
}

// ---------------- launcher ----------------
extern "C" void kernel_launch(void* const* d_in, const int* in_sizes, int n_in,
                              void* d_out, int out_size) {
    (void)in_sizes; (void)n_in; (void)out_size;
    const float2* x          = (const float2*)d_in[0];
    const float2* gamma_attn = (const float2*)d_in[1];
    const float2* Wq         = (const float2*)d_in[2];
    const float2* Wkv        = (const float2*)d_in[3];
    const float2* Wo         = (const float2*)d_in[4];
    const float2* gamma_ff   = (const float2*)d_in[5];
    const float2* W1         = (const float2*)d_in[6];
    const float2* b1         = (const float2*)d_in[7];
    const float*  modb       = (const float*)d_in[8];
    const float2* W2         = (const float2*)d_in[9];
    const float2* b2         = (const float2*)d_in[10];
    const float2* gfin       = (const float2*)d_in[11];

    float2 *px, *phn, *pq, *pkv, *po, *pff;
    cudaGetSymbolAddress((void**)&px,  g_x);
    cudaGetSymbolAddress((void**)&phn, g_hn);
    cudaGetSymbolAddress((void**)&pq,  g_q);
    cudaGetSymbolAddress((void**)&pkv, g_kv);
    cudaGetSymbolAddress((void**)&po,  g_o);
    cudaGetSymbolAddress((void**)&pff, g_ff);

    cudaMemcpyAsync(px, x, sizeof(float2)*MM*DIMC, cudaMemcpyDeviceToDevice);
    ct_rope_init<<<(NN*DHH + 255)/256, 256>>>();

    for (int l = 0; l < NDEPTH; l++) {
        ct_rmsnorm<<<MM, 128>>>(px, gamma_attn + l*DIMC, phn);
        ct_cgemm_tc<<<dim3(INNERC/TBN,   MM/TBM), 256>>>(phn, Wq  + (size_t)l*DIMC*INNERC,   pq,  DIMC, INNERC,   0, nullptr, nullptr);
        ct_cgemm_tc<<<dim3(2*INNERC/TBN, MM/TBM), 256>>>(phn, Wkv + (size_t)l*DIMC*2*INNERC, pkv, DIMC, 2*INNERC, 1, nullptr, nullptr);
        ct_attention_tc4<<<dim3(BB*NHEADS, NN/AQ2), 256>>>();
        ct_cgemm_tc<<<dim3(DIMC/TBN, MM/TBM), 256>>>(po, Wo + (size_t)l*INNERC*DIMC, px, INNERC, DIMC, 2, nullptr, nullptr);
        ct_rmsnorm<<<MM, 128>>>(px, gamma_ff + l*DIMC, phn);
        ct_cgemm_tc<<<dim3(FFC/TBN,  MM/TBM), 256>>>(phn, W1 + (size_t)l*DIMC*FFC, pff, DIMC, FFC, 3, b1 + l*FFC,  modb + l);
        ct_cgemm_tc<<<dim3(DIMC/TBN, MM/TBM), 256>>>(pff, W2 + (size_t)l*FFC*DIMC, px,  FFC,  DIMC, 4, b2 + l*DIMC, nullptr);
    }
    ct_rmsnorm<<<MM, 128>>>(px, gfin, (float2*)d_out);
}

// round 8
// speedup vs baseline: 5.3985x; 1.2875x over previous
#include <cuda_runtime.h>
#include <math.h>
#include <stdint.h>

#define BB     2
#define NN     1024
#define DIMC   512
#define NHEADS 8
#define DHH    64
#define INNERC 512
#define FFC    2048
#define NDEPTH 2
#define MM     (BB*NN)
#define EPSF   1e-6f
#define ATT_SCALE 0.125f

// ---------------- scratch ----------------
__device__ float2 g_x [MM*DIMC];
__device__ float2 g_hn[MM*DIMC];
__device__ float2 g_q [MM*INNERC];
__device__ float2 g_kv[MM*2*INNERC];
__device__ float2 g_o [MM*INNERC];
__device__ float2 g_ff[MM*FFC];
__device__ float2 g_rope[NN*DHH];
__device__ float2 g_wtf[6291456];     // tf32-rounded weights (all layers)

// complex-element offsets into g_wtf
#define OFF_WQ  0
#define OFF_WKV 524288
#define OFF_WO  1572864
#define OFF_W1  2097152
#define OFF_W2  4194304

__device__ __forceinline__ float2 cmulf(float2 a, float2 b) {
    return make_float2(a.x*b.x - a.y*b.y, a.x*b.y + a.y*b.x);
}
__device__ __forceinline__ uint32_t f2tf32(float x) {
    uint32_t u;
    asm("cvt.rna.tf32.f32 %0, %1;" : "=r"(u) : "f"(x));
    return u;
}
__device__ __forceinline__ float tf32f(float x) {
    return __uint_as_float(f2tf32(x));
}
__device__ __forceinline__ void mma_tf32(float* d, const uint32_t* a, const uint32_t* b) {
    asm volatile(
        "mma.sync.aligned.m16n8k8.row.col.f32.tf32.tf32.f32 "
        "{%0,%1,%2,%3},{%4,%5,%6,%7},{%8,%9},{%0,%1,%2,%3};"
        : "+f"(d[0]), "+f"(d[1]), "+f"(d[2]), "+f"(d[3])
        : "r"(a[0]), "r"(a[1]), "r"(a[2]), "r"(a[3]), "r"(b[0]), "r"(b[1]));
}
__device__ __forceinline__ void cp16(uint32_t dst, const void* src) {
    asm volatile("cp.async.cg.shared.global [%0], [%1], 16;" :: "r"(dst), "l"(src));
}
__device__ __forceinline__ void cp_commit() { asm volatile("cp.async.commit_group;"); }
template<int N> __device__ __forceinline__ void cp_wait() {
    asm volatile("cp.async.wait_group %0;" :: "n"(N));
}

// ---------------- weight pre-rounding ----------------
__global__ __launch_bounds__(256) void ct_round_copy(const float4* __restrict__ src,
                                                     float4* __restrict__ dst, int n4) {
    int i = blockIdx.x*blockDim.x + threadIdx.x;
    if (i >= n4) return;
    float4 f = src[i];
    dst[i] = make_float4(tf32f(f.x), tf32f(f.y), tf32f(f.z), tf32f(f.w));
}

// ---------------- rope table ----------------
__global__ void ct_rope_init() {
    int i = blockIdx.x*blockDim.x + threadIdx.x;
    if (i >= NN*DHH) return;
    int n = i / DHH, d = i % DHH;
    double inv = exp(-((double)d / (double)DHH) * log(10000.0));
    double fr  = (double)n * inv;
    g_rope[i] = make_float2((float)cos(fr), (float)sin(fr));
}

// ---------------- complex rmsnorm (optionally tf32-rounds output) ------------
__global__ __launch_bounds__(128) void ct_rmsnorm(const float2* __restrict__ in,
                                                  const float2* __restrict__ gamma,
                                                  float2* __restrict__ out, int rnd) {
    int row = blockIdx.x;
    const float2* xr = in + row*DIMC;
    float ss = 0.f;
    for (int d = threadIdx.x; d < DIMC; d += 128) {
        float2 v = xr[d];
        ss = fmaf(v.x, v.x, ss);
        ss = fmaf(v.y, v.y, ss);
    }
#pragma unroll
    for (int off = 16; off; off >>= 1) ss += __shfl_xor_sync(0xffffffffu, ss, off);
    __shared__ float sred[4];
    if ((threadIdx.x & 31) == 0) sred[threadIdx.x >> 5] = ss;
    __syncthreads();
    ss = sred[0] + sred[1] + sred[2] + sred[3];
    float sc = rsqrtf(ss * (1.f/(float)DIMC) + EPSF);
    for (int d = threadIdx.x; d < DIMC; d += 128) {
        float2 v = xr[d];
        float2 g = gamma[d];
        float re = sc*(v.x*g.x - v.y*g.y);
        float im = sc*(v.x*g.y + v.y*g.x);
        if (rnd) { re = tf32f(re); im = tf32f(im); }
        out[row*DIMC + d] = make_float2(re, im);
    }
}

// ---------------- cp.async double-buffered tf32 complex GEMM -----------------
// Inputs (A and W) are pre-rounded to tf32 by producers. A smem layout [m][k]
// stride KAPAD=20 float2 (conflict-free LDS.64 frags); B [k][n] stride 68.
#define TBM 128
#define TBN 64
#define TBK 16
#define KAPAD 20
#define CG_STAGE 29184   // A: 128*20*8 = 20480  +  B: 16*68*8 = 8704
#define CG_SMEM  (2*CG_STAGE)

__device__ __forceinline__ void epilog(float2* __restrict__ C, int NC, int m, int n,
                                       float re, float im, int epi,
                                       const float2* __restrict__ bias,
                                       const float* __restrict__ modb) {
    int idx = m*NC + n;
    float2 r = make_float2(re, im);
    if (epi == 0) {
        float2 ph = g_rope[(m & (NN-1))*DHH + (n & (DHH-1))];
        float2 t = cmulf(r, ph);
        C[idx] = make_float2(tf32f(t.x), tf32f(t.y));     // Q: attention input
    } else if (epi == 1) {
        if (n < INNERC) {
            float2 ph = g_rope[(m & (NN-1))*DHH + (n & (DHH-1))];
            r = cmulf(r, ph);
        }
        C[idx] = make_float2(tf32f(r.x), tf32f(r.y));     // K|V: attention input
    } else if (epi == 2) {
        float2 c = C[idx];
        C[idx] = make_float2(c.x + r.x, c.y + r.y);       // residual: full fp32
    } else if (epi == 3) {
        float2 bv = bias[n];
        r.x += bv.x; r.y += bv.y;
        float mag = sqrtf(r.x*r.x + r.y*r.y);
        float t = fmaxf(mag + *modb, 0.f);
        float cl = t*t;
        if (mag > 0.f) {
            float s = cl / mag;
            r.x *= s; r.y *= s;
        } else {
            r.x = cl; r.y = 0.f;
        }
        C[idx] = make_float2(tf32f(r.x), tf32f(r.y));     // FF1: W2 GEMM input
    } else {
        float2 bv = bias[n];
        float2 c = C[idx];
        C[idx] = make_float2(c.x + r.x + bv.x, c.y + r.y + bv.y);  // residual
    }
}

__global__ __launch_bounds__(256, 2) void ct_cgemm_tc(const float2* __restrict__ A,
                                                      const float2* __restrict__ W,
                                                      float2* __restrict__ C,
                                                      int K, int NC, int epi,
                                                      const float2* __restrict__ bias,
                                                      const float* __restrict__ modb) {
    extern __shared__ char dynsm[];
    int tid  = threadIdx.x;
    int warp = tid >> 5;
    int lane = tid & 31;
    int g    = lane >> 2;
    int tg   = lane & 3;
    int warp_m = warp & 3;
    int warp_n = warp >> 2;
    int m0 = blockIdx.y * TBM;
    int n0 = blockIdx.x * TBN;

    uint32_t smbase = (uint32_t)__cvta_generic_to_shared(dynsm);

    float cr[2][4][4] = {};
    float ci[2][4][4] = {};

    const int ntiles = K / TBK;

    // stage loader: A tile (128x16 cplx, [m][k] stride 20) + B tile (16x64, [k][n] stride 68)
    auto stageLoad = [&](int s, int k0) {
        uint32_t ab = smbase + s*CG_STAGE;
#pragma unroll
        for (int i = 0; i < 4; i++) {
            int e = tid + i*256;
            int r = e >> 3, c4 = e & 7;
            cp16(ab + (uint32_t)(r*KAPAD + c4*2)*8, &A[(size_t)(m0 + r)*K + k0 + c4*2]);
        }
        uint32_t bb = ab + 20480;
#pragma unroll
        for (int i = 0; i < 2; i++) {
            int e = tid + i*256;
            int r = e >> 5, c4 = e & 31;
            cp16(bb + (uint32_t)(r*68 + c4*2)*8, &W[(size_t)(k0 + r)*NC + n0 + c4*2]);
        }
        cp_commit();
    };

    stageLoad(0, 0);
    for (int kt = 0; kt < ntiles; kt++) {
        if (kt + 1 < ntiles) { stageLoad((kt+1)&1, (kt+1)*TBK); cp_wait<1>(); }
        else                 { cp_wait<0>(); }
        __syncthreads();

        const float2* As_ = reinterpret_cast<const float2*>(dynsm + (kt&1)*CG_STAGE);
        const float2* Bs_ = reinterpret_cast<const float2*>(dynsm + (kt&1)*CG_STAGE + 20480);

#pragma unroll
        for (int ks = 0; ks < TBK; ks += 8) {
            uint32_t ar[2][4], ai[2][4], nai[2][4];
            uint32_t br[4][2], bi[4][2];
#pragma unroll
            for (int mt = 0; mt < 2; mt++) {
                int mb = warp_m*32 + mt*16;
                float2 q0 = As_[(mb + g    )*KAPAD + ks + tg    ];
                float2 q1 = As_[(mb + g + 8)*KAPAD + ks + tg    ];
                float2 q2 = As_[(mb + g    )*KAPAD + ks + tg + 4];
                float2 q3 = As_[(mb + g + 8)*KAPAD + ks + tg + 4];
                ar[mt][0] = __float_as_uint(q0.x); ai[mt][0] = __float_as_uint(q0.y);
                ar[mt][1] = __float_as_uint(q1.x); ai[mt][1] = __float_as_uint(q1.y);
                ar[mt][2] = __float_as_uint(q2.x); ai[mt][2] = __float_as_uint(q2.y);
                ar[mt][3] = __float_as_uint(q3.x); ai[mt][3] = __float_as_uint(q3.y);
#pragma unroll
                for (int t = 0; t < 4; t++) nai[mt][t] = ai[mt][t] ^ 0x80000000u;
            }
#pragma unroll
            for (int nt = 0; nt < 4; nt++) {
                int nb = warp_n*32 + nt*8;
                float2 w0 = Bs_[(ks + tg    )*68 + nb + g];
                float2 w1 = Bs_[(ks + tg + 4)*68 + nb + g];
                br[nt][0] = __float_as_uint(w0.x); bi[nt][0] = __float_as_uint(w0.y);
                br[nt][1] = __float_as_uint(w1.x); bi[nt][1] = __float_as_uint(w1.y);
            }
#pragma unroll
            for (int mt = 0; mt < 2; mt++)
#pragma unroll
                for (int nt = 0; nt < 4; nt++) {
                    mma_tf32(cr[mt][nt], ar[mt],  br[nt]);
                    mma_tf32(cr[mt][nt], nai[mt], bi[nt]);
                    mma_tf32(ci[mt][nt], ar[mt],  bi[nt]);
                    mma_tf32(ci[mt][nt], ai[mt],  br[nt]);
                }
        }
        __syncthreads();
    }

#pragma unroll
    for (int mt = 0; mt < 2; mt++)
#pragma unroll
        for (int nt = 0; nt < 4; nt++)
#pragma unroll
            for (int c = 0; c < 4; c++) {
                int row = m0 + warp_m*32 + mt*16 + g + ((c >= 2) ? 8 : 0);
                int col = n0 + warp_n*32 + nt*8 + 2*tg + (c & 1);
                epilog(C, NC, row, col, cr[mt][nt][c], ci[mt][nt][c], epi, bias, modb);
            }
}

// ---------------- merged-variant attention (cp.async K/V double buffer) -----
#define AQ2 32
#define AK2 16
#define KVP 68
#define PST 20
#define AT_KV_STAGE 17408                 // K[16][68] + V[16][68] float2
#define AT_Q_OFF    (2*AT_KV_STAGE)      // 34816
#define AT_SMEM     (AT_Q_OFF + 32*KVP*8) // 52224

__global__ __launch_bounds__(256, 2) void ct_attention_tc4() {
    extern __shared__ char asmem[];
    float2 (*Qc)[KVP] = reinterpret_cast<float2(*)[KVP]>(asmem + AT_Q_OFF);
    float* Pbase  = reinterpret_cast<float*>(asmem + AT_Q_OFF);  // aliases Qc
    float* planes = reinterpret_cast<float*>(asmem);             // aliases stages

    int bh = blockIdx.x;
    int b  = bh >> 3;
    int h  = bh & 7;
    int q0 = blockIdx.y * AQ2;
    int tid = threadIdx.x, warp = tid >> 5, lane = tid & 31;
    int g = lane >> 2, tg = lane & 3;
    int v  = warp & 3;
    int qh = warp >> 2;
    int m0 = qh * 16;
    float* Ps = Pbase + warp * (16 * PST);

    uint32_t smbase = (uint32_t)__cvta_generic_to_shared(asmem);

    // ---- stage Q (already tf32-rounded by producer) ----
#pragma unroll
    for (int i = 0; i < 4; i++) {
        int e = tid + i*256;
        int row = e >> 5, c4 = e & 31;
        *reinterpret_cast<float4*>(&Qc[row][c4*2]) =
            *reinterpret_cast<const float4*>(
                &g_q[(size_t)(b*NN + q0 + row)*INNERC + h*DHH + c4*2]);
    }
    __syncthreads();

    // ---- Q fragments in registers ----
    uint32_t qa[8][4];
#pragma unroll
    for (int ks = 0; ks < 8; ks++) {
        float2 c0 = Qc[m0 + g    ][ks*8 + tg];
        float2 c1 = Qc[m0 + g + 8][ks*8 + tg];
        float2 c2 = Qc[m0 + g    ][ks*8 + tg + 4];
        float2 c3 = Qc[m0 + g + 8][ks*8 + tg + 4];
        qa[ks][0] = __float_as_uint((v < 2) ? c0.x : c0.y);
        qa[ks][1] = __float_as_uint((v < 2) ? c1.x : c1.y);
        qa[ks][2] = __float_as_uint((v < 2) ? c2.x : c2.y);
        qa[ks][3] = __float_as_uint((v < 2) ? c3.x : c3.y);
    }

    auto loadKV = [&](int s, int kt) {
        uint32_t base = smbase + s*AT_KV_STAGE;
#pragma unroll
        for (int i = 0; i < 2; i++) {
            int e = tid + i*256;
            int row = e >> 5, c4 = e & 31;
            const float2* src = &g_kv[(size_t)(b*NN + kt + row)*2*INNERC + h*DHH + c4*2];
            cp16(base + (uint32_t)(row*KVP + c4*2)*8, src);           // K
            cp16(base + 8704 + (uint32_t)(row*KVP + c4*2)*8, src + INNERC); // V
        }
        cp_commit();
    };

    float o[8][4] = {};
    float lsum_lo = 0.f, lsum_hi = 0.f;
    const int ntiles = NN / AK2;

    loadKV(0, 0);
    for (int t = 0; t < ntiles; t++) {
        if (t + 1 < ntiles) { loadKV((t+1)&1, (t+1)*AK2); cp_wait<1>(); }
        else                { cp_wait<0>(); }
        __syncthreads();

        const float2 (*Kc)[KVP] = reinterpret_cast<const float2(*)[KVP]>(asmem + (t&1)*AT_KV_STAGE);
        const float2 (*Vc)[KVP] = reinterpret_cast<const float2(*)[KVP]>(asmem + (t&1)*AT_KV_STAGE + 8704);

        // ---- S = q·k^T (m16 x n16 x k64) ----
        float sacc[2][4] = {};
#pragma unroll
        for (int ks = 0; ks < 8; ks++) {
#pragma unroll
            for (int nt = 0; nt < 2; nt++) {
                float2 k0 = Kc[nt*8 + g][ks*8 + tg];
                float2 k1 = Kc[nt*8 + g][ks*8 + tg + 4];
                uint32_t bb[2];
                bb[0] = __float_as_uint((v & 1) ? -k0.y : k0.x);
                bb[1] = __float_as_uint((v & 1) ? -k1.y : k1.x);
                mma_tf32(sacc[nt], qa[ks], bb);
            }
        }

        // ---- exp → per-warp P; row-sum partials in registers ----
#pragma unroll
        for (int nt = 0; nt < 2; nt++) {
            float p0 = tf32f(__expf(sacc[nt][0] * ATT_SCALE));
            float p1 = tf32f(__expf(sacc[nt][1] * ATT_SCALE));
            float p2 = tf32f(__expf(sacc[nt][2] * ATT_SCALE));
            float p3 = tf32f(__expf(sacc[nt][3] * ATT_SCALE));
            lsum_lo += p0 + p1;
            lsum_hi += p2 + p3;
            *reinterpret_cast<float2*>(&Ps[(g    )*PST + nt*8 + 2*tg]) = make_float2(p0, p1);
            *reinterpret_cast<float2*>(&Ps[(g + 8)*PST + nt*8 + 2*tg]) = make_float2(p2, p3);
        }
        __syncwarp();

        // ---- O += P·V (m16 x n64 x k16) ----
#pragma unroll
        for (int k8 = 0; k8 < AK2; k8 += 8) {
            uint32_t pa[4];
            pa[0] = __float_as_uint(Ps[(g    )*PST + k8 + tg    ]);
            pa[1] = __float_as_uint(Ps[(g + 8)*PST + k8 + tg    ]);
            pa[2] = __float_as_uint(Ps[(g    )*PST + k8 + tg + 4]);
            pa[3] = __float_as_uint(Ps[(g + 8)*PST + k8 + tg + 4]);
#pragma unroll
            for (int nt = 0; nt < 8; nt++) {
                float2 v0 = Vc[k8 + tg    ][nt*8 + g];
                float2 v1 = Vc[k8 + tg + 4][nt*8 + g];
                uint32_t bb[2];
                bb[0] = __float_as_uint((v < 2) ? v0.x : v0.y);
                bb[1] = __float_as_uint((v < 2) ? v1.x : v1.y);
                mma_tf32(o[nt], pa, bb);
            }
        }
        __syncthreads();
    }

    // ---- finalize row sums, normalize, write variant planes ----
#pragma unroll
    for (int off = 1; off <= 2; off <<= 1) {
        lsum_lo += __shfl_xor_sync(0xffffffffu, lsum_lo, off);
        lsum_hi += __shfl_xor_sync(0xffffffffu, lsum_hi, off);
    }
    float inv_lo = 1.f / lsum_lo;
    float inv_hi = 1.f / lsum_hi;
    float* pl = planes + v * (AQ2 * DHH);
#pragma unroll
    for (int nt = 0; nt < 8; nt++) {
        int col = nt*8 + 2*tg;
        pl[(m0 + g    )*DHH + col    ] = o[nt][0] * inv_lo;
        pl[(m0 + g    )*DHH + col + 1] = o[nt][1] * inv_lo;
        pl[(m0 + g + 8)*DHH + col    ] = o[nt][2] * inv_hi;
        pl[(m0 + g + 8)*DHH + col + 1] = o[nt][3] * inv_hi;
    }
    __syncthreads();

    // ---- combine variants (re = o0 - o3, im = o1 + o2), round for Wo GEMM ----
#pragma unroll
    for (int i = 0; i < 8; i++) {
        int e = tid + i*256;
        int row = e >> 6, d = e & 63;
        float re = planes[             row*DHH + d] - planes[3*AQ2*DHH + row*DHH + d];
        float im = planes[  AQ2*DHH + row*DHH + d] + planes[2*AQ2*DHH + row*DHH + d];
        g_o[(size_t)(b*NN + q0 + row)*INNERC + h*DHH + d] =
            make_float2(tf32f(re), tf32f(im));
    }
}

// ---------------- launcher ----------------
extern "C" void kernel_launch(void* const* d_in, const int* in_sizes, int n_in,
                              void* d_out, int out_size) {
    (void)in_sizes; (void)n_in; (void)out_size;
    const float2* x          = (const float2*)d_in[0];
    const float2* gamma_attn = (const float2*)d_in[1];
    const float2* Wq         = (const float2*)d_in[2];
    const float2* Wkv        = (const float2*)d_in[3];
    const float2* Wo         = (const float2*)d_in[4];
    const float2* gamma_ff   = (const float2*)d_in[5];
    const float2* W1         = (const float2*)d_in[6];
    const float2* b1         = (const float2*)d_in[7];
    const float*  modb       = (const float*)d_in[8];
    const float2* W2         = (const float2*)d_in[9];
    const float2* b2         = (const float2*)d_in[10];
    const float2* gfin       = (const float2*)d_in[11];

    float2 *px, *phn, *pq, *pkv, *po, *pff, *pw;
    cudaGetSymbolAddress((void**)&px,  g_x);
    cudaGetSymbolAddress((void**)&phn, g_hn);
    cudaGetSymbolAddress((void**)&pq,  g_q);
    cudaGetSymbolAddress((void**)&pkv, g_kv);
    cudaGetSymbolAddress((void**)&po,  g_o);
    cudaGetSymbolAddress((void**)&pff, g_ff);
    cudaGetSymbolAddress((void**)&pw,  g_wtf);

    cudaFuncSetAttribute(ct_cgemm_tc, cudaFuncAttributeMaxDynamicSharedMemorySize, CG_SMEM);
    cudaFuncSetAttribute(ct_attention_tc4, cudaFuncAttributeMaxDynamicSharedMemorySize, AT_SMEM);

    cudaMemcpyAsync(px, x, sizeof(float2)*MM*DIMC, cudaMemcpyDeviceToDevice);
    ct_rope_init<<<(NN*DHH + 255)/256, 256>>>();

    // pre-round all weights (float4 = 2 complex)
    struct { const float2* s; size_t off; int n4; } wcp[5] = {
        {Wq,  OFF_WQ,  NDEPTH*DIMC*INNERC/2},
        {Wkv, OFF_WKV, NDEPTH*DIMC*2*INNERC/2},
        {Wo,  OFF_WO,  NDEPTH*INNERC*DIMC/2},
        {W1,  OFF_W1,  NDEPTH*DIMC*FFC/2},
        {W2,  OFF_W2,  NDEPTH*FFC*DIMC/2},
    };
    for (int i = 0; i < 5; i++)
        ct_round_copy<<<(wcp[i].n4 + 255)/256, 256>>>(
            (const float4*)wcp[i].s, (float4*)(pw + wcp[i].off), wcp[i].n4);

    for (int l = 0; l < NDEPTH; l++) {
        ct_rmsnorm<<<MM, 128>>>(px, gamma_attn + l*DIMC, phn, 1);
        ct_cgemm_tc<<<dim3(INNERC/TBN,   MM/TBM), 256, CG_SMEM>>>(
            phn, pw + OFF_WQ  + (size_t)l*DIMC*INNERC,   pq,  DIMC, INNERC,   0, nullptr, nullptr);
        ct_cgemm_tc<<<dim3(2*INNERC/TBN, MM/TBM), 256, CG_SMEM>>>(
            phn, pw + OFF_WKV + (size_t)l*DIMC*2*INNERC, pkv, DIMC, 2*INNERC, 1, nullptr, nullptr);
        ct_attention_tc4<<<dim3(BB*NHEADS, NN/AQ2), 256, AT_SMEM>>>();
        ct_cgemm_tc<<<dim3(DIMC/TBN, MM/TBM), 256, CG_SMEM>>>(
            po, pw + OFF_WO + (size_t)l*INNERC*DIMC, px, INNERC, DIMC, 2, nullptr, nullptr);
        ct_rmsnorm<<<MM, 128>>>(px, gamma_ff + l*DIMC, phn, 1);
        ct_cgemm_tc<<<dim3(FFC/TBN,  MM/TBM), 256, CG_SMEM>>>(
            phn, pw + OFF_W1 + (size_t)l*DIMC*FFC, pff, DIMC, FFC, 3, b1 + l*FFC,  modb + l);
        ct_cgemm_tc<<<dim3(DIMC/TBN, MM/TBM), 256, CG_SMEM>>>(
            pff, pw + OFF_W2 + (size_t)l*FFC*DIMC, px,  FFC,  DIMC, 4, b2 + l*DIMC, nullptr);
    }
    ct_rmsnorm<<<MM, 128>>>(px, gfin, (float2*)d_out, 0);
}